// round 2
// baseline (speedup 1.0000x reference)
#include <cuda_runtime.h>
#include <math.h>

#define BT_ROWS 65536   // B*T
#define C_DIM   384
#define H_DIM   64
#define T_DIM   256
#define B_DIM   256

// Scratch for q,k,v projections: 3 * 65536 * 64 floats = 50.3 MB
__device__ float g_qkv[3ull * BT_ROWS * H_DIM];

// ---------------------------------------------------------------------------
// Kernel 1: fused QKV projection.  qkv[sel] = x @ W_sel
// x: [65536, 384] row-major, W: [384, 64] row-major.
// BM=128, BN=64, BK=16, 256 threads, 8x4 per-thread tile.
// ---------------------------------------------------------------------------
__global__ __launch_bounds__(256) void proj_kernel(
    const float* __restrict__ x,
    const float* __restrict__ Wq,
    const float* __restrict__ Wk,
    const float* __restrict__ Wv)
{
    constexpr int BM = 128, BN = 64, BK = 16;
    __shared__ float xs[BK][BM];   // transposed x tile: xs[k][m]
    __shared__ float ws[BK][BN];   // ws[k][n]

    const float* W = (blockIdx.y == 0) ? Wq : (blockIdx.y == 1) ? Wk : Wv;
    float* out = g_qkv + (size_t)blockIdx.y * BT_ROWS * H_DIM;

    const int m0  = blockIdx.x * BM;
    const int tid = threadIdx.x;
    const int tx  = tid & 15;   // n direction (16 threads * 4 cols)
    const int ty  = tid >> 4;   // m direction (16 threads * 8 rows)

    float acc[8][4];
    #pragma unroll
    for (int i = 0; i < 8; i++)
        #pragma unroll
        for (int j = 0; j < 4; j++) acc[i][j] = 0.f;

    for (int kb = 0; kb < C_DIM; kb += BK) {
        // Load x tile [BM x BK] transposed into xs[k][m].
        // 128 rows * 4 float4 = 512 float4; 2 per thread.
        #pragma unroll
        for (int r = 0; r < 2; r++) {
            int idx = tid + r * 256;      // float4 index 0..511
            int row = idx >> 2;           // 0..127
            int kg  = (idx & 3) << 2;     // 0,4,8,12
            float4 xv = *reinterpret_cast<const float4*>(
                &x[(size_t)(m0 + row) * C_DIM + kb + kg]);
            xs[kg + 0][row] = xv.x;
            xs[kg + 1][row] = xv.y;
            xs[kg + 2][row] = xv.z;
            xs[kg + 3][row] = xv.w;
        }
        // Load W tile [BK x BN] = 1024 floats = 256 float4; 1 per thread.
        {
            int kr = tid >> 4;            // 0..15
            int ng = (tid & 15) << 2;     // 0..60
            *reinterpret_cast<float4*>(&ws[kr][ng]) =
                *reinterpret_cast<const float4*>(&W[(size_t)(kb + kr) * H_DIM + ng]);
        }
        __syncthreads();

        #pragma unroll
        for (int kk = 0; kk < BK; kk++) {
            float4 a0 = *reinterpret_cast<const float4*>(&xs[kk][ty * 8]);
            float4 a1 = *reinterpret_cast<const float4*>(&xs[kk][ty * 8 + 4]);
            float4 bv = *reinterpret_cast<const float4*>(&ws[kk][tx * 4]);
            float am[8] = {a0.x, a0.y, a0.z, a0.w, a1.x, a1.y, a1.z, a1.w};
            float bn[4] = {bv.x, bv.y, bv.z, bv.w};
            #pragma unroll
            for (int i = 0; i < 8; i++)
                #pragma unroll
                for (int j = 0; j < 4; j++)
                    acc[i][j] += am[i] * bn[j];
        }
        __syncthreads();
    }

    #pragma unroll
    for (int i = 0; i < 8; i++) {
        float4 o = make_float4(acc[i][0], acc[i][1], acc[i][2], acc[i][3]);
        *reinterpret_cast<float4*>(
            &out[(size_t)(m0 + ty * 8 + i) * H_DIM + tx * 4]) = o;
    }
}

// ---------------------------------------------------------------------------
// Kernel 2: causal attention, one thread per query row.
// grid (B, 2), 128 threads/block; thread tid in parity block p owns query
// 2*tid + p (interleaved for causal load balance between the two blocks).
// Exact softmax in one pass: scores are bounded (|q.k|*scale <~ 4 for
// N(0,1)-scaled projections), so no max subtraction is needed — the result
// is mathematically identical to the reference softmax.
// Inner loop processes 2 keys/iter for independent exp/FMA chains (ILP).
// ---------------------------------------------------------------------------
__global__ __launch_bounds__(128) void attn_kernel(float* __restrict__ out)
{
    constexpr int TILE = 64;
    __shared__ float ks[TILE][H_DIM];
    __shared__ float vs[TILE][H_DIM];

    const int b   = blockIdx.x;
    const int par = blockIdx.y;
    const int tid = threadIdx.x;
    const int qi  = 2 * tid + par;          // query index 0..255

    const float* qp = g_qkv + (size_t)b * T_DIM * H_DIM;
    const float* kp = g_qkv + (size_t)BT_ROWS * H_DIM + (size_t)b * T_DIM * H_DIM;
    const float* vp = g_qkv + 2ull * BT_ROWS * H_DIM + (size_t)b * T_DIM * H_DIM;

    const float scale = 0.05103103630798288f;   // 384^-0.5

    float4 qr[16];
    #pragma unroll
    for (int i = 0; i < 16; i++)
        qr[i] = *reinterpret_cast<const float4*>(&qp[(size_t)qi * H_DIM + i * 4]);

    float4 acc[16];
    #pragma unroll
    for (int i = 0; i < 16; i++) acc[i] = make_float4(0.f, 0.f, 0.f, 0.f);
    float sumexp = 0.f;

    for (int t0 = 0; t0 < T_DIM; t0 += TILE) {
        // Stage K and V tiles: 64x64 floats each = 1024 float4; 8 per thread.
        #pragma unroll
        for (int r = 0; r < 8; r++) {
            int idx = tid + r * 128;        // float4 index
            int row = idx >> 4;
            int cg  = (idx & 15) << 2;
            *reinterpret_cast<float4*>(&ks[row][cg]) =
                *reinterpret_cast<const float4*>(&kp[(size_t)(t0 + row) * H_DIM + cg]);
            *reinterpret_cast<float4*>(&vs[row][cg]) =
                *reinterpret_cast<const float4*>(&vp[(size_t)(t0 + row) * H_DIM + cg]);
        }
        __syncthreads();

        int jmax = qi - t0 + 1;             // causal: keys t0..qi (local count)
        if (jmax > TILE) jmax = TILE;
        if (jmax < 0) jmax = 0;

        int j = 0;
        // 2 keys per iteration: two independent score/exp/accumulate chains.
        for (; j + 2 <= jmax; j += 2) {
            const float4* k0 = reinterpret_cast<const float4*>(ks[j]);
            const float4* k1 = reinterpret_cast<const float4*>(ks[j + 1]);
            float s0 = 0.f, s1 = 0.f;
            #pragma unroll
            for (int i = 0; i < 16; i++) {
                float4 ka = k0[i];
                float4 kb = k1[i];
                s0 += qr[i].x * ka.x + qr[i].y * ka.y +
                      qr[i].z * ka.z + qr[i].w * ka.w;
                s1 += qr[i].x * kb.x + qr[i].y * kb.y +
                      qr[i].z * kb.z + qr[i].w * kb.w;
            }
            float e0 = __expf(s0 * scale);
            float e1 = __expf(s1 * scale);
            sumexp += e0 + e1;
            const float4* v0 = reinterpret_cast<const float4*>(vs[j]);
            const float4* v1 = reinterpret_cast<const float4*>(vs[j + 1]);
            #pragma unroll
            for (int i = 0; i < 16; i++) {
                float4 va = v0[i];
                float4 vb = v1[i];
                acc[i].x += e0 * va.x + e1 * vb.x;
                acc[i].y += e0 * va.y + e1 * vb.y;
                acc[i].z += e0 * va.z + e1 * vb.z;
                acc[i].w += e0 * va.w + e1 * vb.w;
            }
        }
        // Remainder (at most 1 key).
        for (; j < jmax; j++) {
            const float4* krow = reinterpret_cast<const float4*>(ks[j]);
            float s = 0.f;
            #pragma unroll
            for (int i = 0; i < 16; i++) {
                float4 kk = krow[i];
                s += qr[i].x * kk.x + qr[i].y * kk.y +
                     qr[i].z * kk.z + qr[i].w * kk.w;
            }
            float e = __expf(s * scale);
            sumexp += e;
            const float4* vrow = reinterpret_cast<const float4*>(vs[j]);
            #pragma unroll
            for (int i = 0; i < 16; i++) {
                float4 vv = vrow[i];
                acc[i].x += e * vv.x;
                acc[i].y += e * vv.y;
                acc[i].z += e * vv.z;
                acc[i].w += e * vv.w;
            }
        }
        __syncthreads();
    }

    const float inv = 1.f / sumexp;
    #pragma unroll
    for (int i = 0; i < 16; i++) {
        float4 o = make_float4(acc[i].x * inv, acc[i].y * inv,
                               acc[i].z * inv, acc[i].w * inv);
        *reinterpret_cast<float4*>(
            &out[((size_t)b * T_DIM + qi) * H_DIM + i * 4]) = o;
    }
}

// ---------------------------------------------------------------------------
extern "C" void kernel_launch(void* const* d_in, const int* in_sizes, int n_in,
                              void* d_out, int out_size)
{
    const float* x  = (const float*)d_in[0];
    const float* Wq = (const float*)d_in[1];
    const float* Wk = (const float*)d_in[2];
    const float* Wv = (const float*)d_in[3];
    float* out = (float*)d_out;

    proj_kernel<<<dim3(BT_ROWS / 128, 3), 256>>>(x, Wq, Wk, Wv);
    attn_kernel<<<dim3(B_DIM, 2), 128>>>(out);
}

// round 3
// speedup vs baseline: 1.3128x; 1.3128x over previous
#include <cuda_runtime.h>
#include <math.h>

#define BT_ROWS 65536   // B*T
#define C_DIM   384
#define H_DIM   64
#define T_DIM   256
#define B_DIM   256

// Scratch for q,k,v projections: 3 * 65536 * 64 floats = 50.3 MB
__device__ float g_qkv[3ull * BT_ROWS * H_DIM];

// ---------------------------------------------------------------------------
// Kernel 1: fused QKV projection.  qkv[sel] = x @ W_sel
// x: [65536, 384] row-major, W: [384, 64] row-major.
// BM=256, BN=64, BK=16, 256 threads, 8x8 per-thread tile.
// ---------------------------------------------------------------------------
__global__ __launch_bounds__(256) void proj_kernel(
    const float* __restrict__ x,
    const float* __restrict__ Wq,
    const float* __restrict__ Wk,
    const float* __restrict__ Wv)
{
    constexpr int BM = 256, BK = 16;
    __shared__ float xs[BK][BM];   // transposed x tile: xs[k][m]  (16 KB)
    __shared__ float ws[BK][H_DIM];// ws[k][n]                     (4 KB)

    const float* W = (blockIdx.y == 0) ? Wq : (blockIdx.y == 1) ? Wk : Wv;
    float* out = g_qkv + (size_t)blockIdx.y * BT_ROWS * H_DIM;

    const int m0  = blockIdx.x * BM;
    const int tid = threadIdx.x;
    const int tx  = tid & 7;    // n direction: 8 threads * 8 cols = 64
    const int ty  = tid >> 3;   // m direction: 32 threads * 8 rows = 256

    float acc[8][8];
    #pragma unroll
    for (int i = 0; i < 8; i++)
        #pragma unroll
        for (int j = 0; j < 8; j++) acc[i][j] = 0.f;

    for (int kb = 0; kb < C_DIM; kb += BK) {
        // x tile [BM x BK] transposed into xs[k][m]: 1024 float4, 4/thread.
        #pragma unroll
        for (int r = 0; r < 4; r++) {
            int idx = tid + r * 256;      // float4 index 0..1023
            int row = idx >> 2;           // 0..255
            int kg  = (idx & 3) << 2;     // 0,4,8,12
            float4 xv = *reinterpret_cast<const float4*>(
                &x[(size_t)(m0 + row) * C_DIM + kb + kg]);
            xs[kg + 0][row] = xv.x;
            xs[kg + 1][row] = xv.y;
            xs[kg + 2][row] = xv.z;
            xs[kg + 3][row] = xv.w;
        }
        // W tile [BK x 64] = 256 float4; 1 per thread.
        {
            int kr = tid >> 4;            // 0..15
            int ng = (tid & 15) << 2;     // 0..60
            *reinterpret_cast<float4*>(&ws[kr][ng]) =
                *reinterpret_cast<const float4*>(&W[(size_t)(kb + kr) * H_DIM + ng]);
        }
        __syncthreads();

        #pragma unroll
        for (int kk = 0; kk < BK; kk++) {
            float4 a0 = *reinterpret_cast<const float4*>(&xs[kk][ty * 8]);
            float4 a1 = *reinterpret_cast<const float4*>(&xs[kk][ty * 8 + 4]);
            float4 b0 = *reinterpret_cast<const float4*>(&ws[kk][tx * 8]);
            float4 b1 = *reinterpret_cast<const float4*>(&ws[kk][tx * 8 + 4]);
            float am[8] = {a0.x, a0.y, a0.z, a0.w, a1.x, a1.y, a1.z, a1.w};
            float bn[8] = {b0.x, b0.y, b0.z, b0.w, b1.x, b1.y, b1.z, b1.w};
            #pragma unroll
            for (int i = 0; i < 8; i++)
                #pragma unroll
                for (int j = 0; j < 8; j++)
                    acc[i][j] += am[i] * bn[j];
        }
        __syncthreads();
    }

    #pragma unroll
    for (int i = 0; i < 8; i++) {
        float* orow = &out[(size_t)(m0 + ty * 8 + i) * H_DIM + tx * 8];
        *reinterpret_cast<float4*>(orow) =
            make_float4(acc[i][0], acc[i][1], acc[i][2], acc[i][3]);
        *reinterpret_cast<float4*>(orow + 4) =
            make_float4(acc[i][4], acc[i][5], acc[i][6], acc[i][7]);
    }
}

// ---------------------------------------------------------------------------
// Kernel 2: causal attention as two register-blocked GEMMs per key tile.
// Block = (qt, b): 64 queries of batch b. 256 threads, 4x4 per-thread tiles.
//   S = Q K^T  (inner dim H=64), exp+causal mask in registers,
//   P staged through smem (reuses K buffer), O += P V (inner dim 64),
//   single exact softmax pass (scores bounded -> no max subtraction),
//   sumexp reduced once at the end.
// ---------------------------------------------------------------------------
__global__ __launch_bounds__(256) void attn_kernel(float* __restrict__ out)
{
    __shared__ float Qs[64][H_DIM];    // [q][h]        16 KB
    __shared__ float KPs[64][64];      // K as [h][kc]; reused as P [q][k]
    __shared__ float Vs[64][H_DIM];    // [k][h]        16 KB

    const int b   = blockIdx.y;
    const int qt  = 3 - blockIdx.x;        // heavy tiles first
    const int tid = threadIdx.x;
    const int tx  = tid & 15;              // key/h cols: 16 * 4 = 64
    const int ty  = tid >> 4;              // query rows: 16 * 4 = 64

    const float* qp = g_qkv + (size_t)b * T_DIM * H_DIM;
    const float* kp = g_qkv + (size_t)BT_ROWS * H_DIM + (size_t)b * T_DIM * H_DIM;
    const float* vp = g_qkv + 2ull * BT_ROWS * H_DIM + (size_t)b * T_DIM * H_DIM;

    const float scale = 0.05103103630798288f;   // 384^-0.5

    // Load Q tile [64 x 64]: 1024 float4, 4/thread.
    #pragma unroll
    for (int r = 0; r < 4; r++) {
        int idx = tid + r * 256;
        int row = idx >> 4;
        int cg  = (idx & 15) << 2;
        *reinterpret_cast<float4*>(&Qs[row][cg]) =
            *reinterpret_cast<const float4*>(
                &qp[(size_t)(qt * 64 + row) * H_DIM + cg]);
    }

    float acc[4][4];
    #pragma unroll
    for (int i = 0; i < 4; i++)
        #pragma unroll
        for (int j = 0; j < 4; j++) acc[i][j] = 0.f;
    float se[4] = {0.f, 0.f, 0.f, 0.f};

    for (int kt = 0; kt <= qt; kt++) {
        // Load K tile transposed into KPs[h][kc], V tile into Vs[k][h].
        #pragma unroll
        for (int r = 0; r < 4; r++) {
            int idx = tid + r * 256;
            int row = idx >> 4;              // key index 0..63
            int cg  = (idx & 15) << 2;       // h group
            float4 kv = *reinterpret_cast<const float4*>(
                &kp[(size_t)(kt * 64 + row) * H_DIM + cg]);
            KPs[cg + 0][row] = kv.x;
            KPs[cg + 1][row] = kv.y;
            KPs[cg + 2][row] = kv.z;
            KPs[cg + 3][row] = kv.w;
            *reinterpret_cast<float4*>(&Vs[row][cg]) =
                *reinterpret_cast<const float4*>(
                    &vp[(size_t)(kt * 64 + row) * H_DIM + cg]);
        }
        __syncthreads();

        // S = Q K^T : per-thread 4x4, a = broadcast scalar, b = float4.
        float p[4][4];
        #pragma unroll
        for (int i = 0; i < 4; i++)
            #pragma unroll
            for (int j = 0; j < 4; j++) p[i][j] = 0.f;

        #pragma unroll 8
        for (int hh = 0; hh < H_DIM; hh++) {
            float a0 = Qs[ty * 4 + 0][hh];
            float a1 = Qs[ty * 4 + 1][hh];
            float a2 = Qs[ty * 4 + 2][hh];
            float a3 = Qs[ty * 4 + 3][hh];
            float4 bv = *reinterpret_cast<const float4*>(&KPs[hh][tx * 4]);
            p[0][0] += a0 * bv.x; p[0][1] += a0 * bv.y; p[0][2] += a0 * bv.z; p[0][3] += a0 * bv.w;
            p[1][0] += a1 * bv.x; p[1][1] += a1 * bv.y; p[1][2] += a1 * bv.z; p[1][3] += a1 * bv.w;
            p[2][0] += a2 * bv.x; p[2][1] += a2 * bv.y; p[2][2] += a2 * bv.z; p[2][3] += a2 * bv.w;
            p[3][0] += a3 * bv.x; p[3][1] += a3 * bv.y; p[3][2] += a3 * bv.z; p[3][3] += a3 * bv.w;
        }

        // Causal mask (diagonal tile only: kt == qt) + exp + sumexp partials.
        const bool diag = (kt == qt);
        #pragma unroll
        for (int i = 0; i < 4; i++) {
            int ql = ty * 4 + i;
            #pragma unroll
            for (int j = 0; j < 4; j++) {
                int kl = tx * 4 + j;
                float e = (!diag || kl <= ql) ? __expf(p[i][j] * scale) : 0.f;
                p[i][j] = e;
                se[i] += e;
            }
        }
        __syncthreads();   // done reading K from KPs

        // Stage P into KPs as [q][k].
        #pragma unroll
        for (int i = 0; i < 4; i++)
            *reinterpret_cast<float4*>(&KPs[ty * 4 + i][tx * 4]) =
                make_float4(p[i][0], p[i][1], p[i][2], p[i][3]);
        __syncthreads();

        // O += P V : per-thread 4x4, a = broadcast scalar, b = float4.
        #pragma unroll 8
        for (int kk = 0; kk < 64; kk++) {
            float a0 = KPs[ty * 4 + 0][kk];
            float a1 = KPs[ty * 4 + 1][kk];
            float a2 = KPs[ty * 4 + 2][kk];
            float a3 = KPs[ty * 4 + 3][kk];
            float4 bv = *reinterpret_cast<const float4*>(&Vs[kk][tx * 4]);
            acc[0][0] += a0 * bv.x; acc[0][1] += a0 * bv.y; acc[0][2] += a0 * bv.z; acc[0][3] += a0 * bv.w;
            acc[1][0] += a1 * bv.x; acc[1][1] += a1 * bv.y; acc[1][2] += a1 * bv.z; acc[1][3] += a1 * bv.w;
            acc[2][0] += a2 * bv.x; acc[2][1] += a2 * bv.y; acc[2][2] += a2 * bv.z; acc[2][3] += a2 * bv.w;
            acc[3][0] += a3 * bv.x; acc[3][1] += a3 * bv.y; acc[3][2] += a3 * bv.z; acc[3][3] += a3 * bv.w;
        }
        __syncthreads();   // before next tile overwrites KPs/Vs
    }

    // Reduce sumexp across the 16 tx-threads of each query row (reuse Qs).
    float* red = &Qs[0][0];    // 64 rows * 16 partials
    #pragma unroll
    for (int i = 0; i < 4; i++)
        red[(ty * 4 + i) * 16 + tx] = se[i];
    __syncthreads();

    float inv[4];
    #pragma unroll
    for (int i = 0; i < 4; i++) {
        float s = 0.f;
        #pragma unroll
        for (int t = 0; t < 16; t++) s += red[(ty * 4 + i) * 16 + t];
        inv[i] = 1.f / s;
    }

    #pragma unroll
    for (int i = 0; i < 4; i++) {
        *reinterpret_cast<float4*>(
            &out[((size_t)b * T_DIM + qt * 64 + ty * 4 + i) * H_DIM + tx * 4]) =
            make_float4(acc[i][0] * inv[i], acc[i][1] * inv[i],
                        acc[i][2] * inv[i], acc[i][3] * inv[i]);
    }
}

// ---------------------------------------------------------------------------
extern "C" void kernel_launch(void* const* d_in, const int* in_sizes, int n_in,
                              void* d_out, int out_size)
{
    const float* x  = (const float*)d_in[0];
    const float* Wq = (const float*)d_in[1];
    const float* Wk = (const float*)d_in[2];
    const float* Wv = (const float*)d_in[3];
    float* out = (float*)d_out;

    proj_kernel<<<dim3(BT_ROWS / 256, 3), 256>>>(x, Wq, Wk, Wv);
    attn_kernel<<<dim3(4, B_DIM), 256>>>(out);
}

// round 8
// speedup vs baseline: 2.0228x; 1.5409x over previous
#include <cuda_runtime.h>
#include <cuda_bf16.h>
#include <stdint.h>

#define BT_ROWS 65536   // B*T
#define C_DIM   384
#define H_DIM   64
#define T_DIM   256
#define B_DIM   256
#define N_TOT   192     // q|k|v fused N

// fp32 q,k,v: 3 * 65536 * 64 floats = 50.3 MB
__device__ float g_qkv[3ull * BT_ROWS * H_DIM];
// Fused W in [k][n] (n = mat*64+h), bf16 hi and lo planes.
__device__ __nv_bfloat16 g_wb_hi[C_DIM * N_TOT];
__device__ __nv_bfloat16 g_wb_lo[C_DIM * N_TOT];

__device__ __forceinline__ uint32_t smem_u32(const void* p) {
    uint32_t a;
    asm("{ .reg .u64 t; cvta.to.shared.u64 t, %1; cvt.u32.u64 %0, t; }"
        : "=r"(a) : "l"(p));
    return a;
}

// ---------------------------------------------------------------------------
// Kernel 0: W -> bf16 hi/lo, fused [k][n] layout.
// ---------------------------------------------------------------------------
__global__ void wprep_kernel(const float* __restrict__ Wq,
                             const float* __restrict__ Wk,
                             const float* __restrict__ Wv)
{
    int idx = blockIdx.x * blockDim.x + threadIdx.x;   // over 384*192
    if (idx >= C_DIM * N_TOT) return;
    int k = idx / N_TOT, n = idx % N_TOT;
    int mat = n >> 6, h = n & 63;
    const float* W = (mat == 0) ? Wq : (mat == 1) ? Wk : Wv;
    float v = W[(size_t)k * H_DIM + h];
    __nv_bfloat16 hi = __float2bfloat16(v);
    __nv_bfloat16 lo = __float2bfloat16(v - __bfloat162float(hi));
    g_wb_hi[idx] = hi;
    g_wb_lo[idx] = lo;
}

// ---------------------------------------------------------------------------
// Kernel 1: fused QKV projection via mma.sync bf16 (3-term hi/lo split).
// GEMM [65536, 192, 384]. Block tile 128x192, 8 warps (4m x 2n),
// warp tile 32x96 = 2 (m16) x 12 (n8) C fragments, fp32 accumulate.
// K chunk = 32 staged in smem (A as bf16 hi/lo pad-40, B pad-208).
// ---------------------------------------------------------------------------
__global__ __launch_bounds__(256) void proj_mma_kernel(const float* __restrict__ x)
{
    constexpr int APAD = 40;    // elements per A row (32 + 8 pad)
    constexpr int BPAD = 208;   // elements per B row (192 + 16 pad)
    __shared__ __align__(16) __nv_bfloat16 Ahi[128 * APAD];
    __shared__ __align__(16) __nv_bfloat16 Alo[128 * APAD];
    __shared__ __align__(16) __nv_bfloat16 Bhi[32 * BPAD];
    __shared__ __align__(16) __nv_bfloat16 Blo[32 * BPAD];

    const int tid  = threadIdx.x;
    const int lane = tid & 31;
    const int wid  = tid >> 5;
    const int m0   = blockIdx.x * 128;
    const int wm   = (wid & 3) * 32;    // warp m offset
    const int wn   = (wid >> 2) * 96;   // warp n offset

    float c[2][12][4];
    #pragma unroll
    for (int mt = 0; mt < 2; mt++)
        #pragma unroll
        for (int nt = 0; nt < 12; nt++)
            #pragma unroll
            for (int r = 0; r < 4; r++) c[mt][nt][r] = 0.f;

    const uint32_t a_hi_base = smem_u32(Ahi);
    const uint32_t a_lo_base = smem_u32(Alo);
    const uint32_t b_hi_base = smem_u32(Bhi);
    const uint32_t b_lo_base = smem_u32(Blo);

    for (int kb = 0; kb < C_DIM; kb += 32) {
        // ---- Stage A: x[128 x 32] fp32 -> bf16 hi/lo. 1024 float4, 4/thr.
        #pragma unroll
        for (int r = 0; r < 4; r++) {
            int idx = tid + r * 256;          // 0..1023
            int row = idx >> 3;               // 0..127
            int f4  = idx & 7;                // 0..7
            float4 xv = *reinterpret_cast<const float4*>(
                &x[(size_t)(m0 + row) * C_DIM + kb + f4 * 4]);
            __nv_bfloat16 h0 = __float2bfloat16(xv.x);
            __nv_bfloat16 h1 = __float2bfloat16(xv.y);
            __nv_bfloat16 h2 = __float2bfloat16(xv.z);
            __nv_bfloat16 h3 = __float2bfloat16(xv.w);
            __nv_bfloat16 l0 = __float2bfloat16(xv.x - __bfloat162float(h0));
            __nv_bfloat16 l1 = __float2bfloat16(xv.y - __bfloat162float(h1));
            __nv_bfloat16 l2 = __float2bfloat16(xv.z - __bfloat162float(h2));
            __nv_bfloat16 l3 = __float2bfloat16(xv.w - __bfloat162float(h3));
            ushort4 hs = make_ushort4(
                reinterpret_cast<unsigned short&>(h0), reinterpret_cast<unsigned short&>(h1),
                reinterpret_cast<unsigned short&>(h2), reinterpret_cast<unsigned short&>(h3));
            ushort4 ls = make_ushort4(
                reinterpret_cast<unsigned short&>(l0), reinterpret_cast<unsigned short&>(l1),
                reinterpret_cast<unsigned short&>(l2), reinterpret_cast<unsigned short&>(l3));
            *reinterpret_cast<ushort4*>(&Ahi[row * APAD + f4 * 4]) = hs;
            *reinterpret_cast<ushort4*>(&Alo[row * APAD + f4 * 4]) = ls;
        }
        // ---- Stage B: W[32 x 192] hi/lo. Row = 24 uint4 units; 768 total.
        #pragma unroll
        for (int r = 0; r < 3; r++) {
            int idx = tid + r * 256;          // 0..767
            int row = idx / 24;               // 0..31
            int u   = idx % 24;               // 16B unit (8 el), 24/row
            uint4 sh = *reinterpret_cast<const uint4*>(
                &g_wb_hi[(size_t)(kb + row) * N_TOT + u * 8]);
            uint4 sl = *reinterpret_cast<const uint4*>(
                &g_wb_lo[(size_t)(kb + row) * N_TOT + u * 8]);
            *reinterpret_cast<uint4*>(&Bhi[row * BPAD + u * 8]) = sh;
            *reinterpret_cast<uint4*>(&Blo[row * BPAD + u * 8]) = sl;
        }
        __syncthreads();

        // ---- Compute: 2 k16-steps per chunk.
        #pragma unroll
        for (int st = 0; st < 2; st++) {
            uint32_t ah[2][4], al[2][4];
            #pragma unroll
            for (int mt = 0; mt < 2; mt++) {
                int arow = wm + mt * 16 + (lane & 15);
                uint32_t abyte = (uint32_t)(arow * APAD + st * 16 + ((lane >> 4) << 3)) * 2;
                asm volatile(
                    "ldmatrix.sync.aligned.m8n8.x4.shared.b16 {%0,%1,%2,%3}, [%4];"
                    : "=r"(ah[mt][0]), "=r"(ah[mt][1]), "=r"(ah[mt][2]), "=r"(ah[mt][3])
                    : "r"(a_hi_base + abyte));
                asm volatile(
                    "ldmatrix.sync.aligned.m8n8.x4.shared.b16 {%0,%1,%2,%3}, [%4];"
                    : "=r"(al[mt][0]), "=r"(al[mt][1]), "=r"(al[mt][2]), "=r"(al[mt][3])
                    : "r"(a_lo_base + abyte));
            }
            uint32_t bbyte = (uint32_t)((st * 16 + (lane & 15)) * BPAD + wn) * 2;
            #pragma unroll
            for (int nt = 0; nt < 12; nt++) {
                uint32_t bh0, bh1, bl0, bl1;
                asm volatile(
                    "ldmatrix.sync.aligned.m8n8.x2.trans.shared.b16 {%0,%1}, [%2];"
                    : "=r"(bh0), "=r"(bh1) : "r"(b_hi_base + bbyte + nt * 16));
                asm volatile(
                    "ldmatrix.sync.aligned.m8n8.x2.trans.shared.b16 {%0,%1}, [%2];"
                    : "=r"(bl0), "=r"(bl1) : "r"(b_lo_base + bbyte + nt * 16));
                #pragma unroll
                for (int mt = 0; mt < 2; mt++) {
                    asm volatile(
                        "mma.sync.aligned.m16n8k16.row.col.f32.bf16.bf16.f32 "
                        "{%0,%1,%2,%3}, {%4,%5,%6,%7}, {%8,%9}, {%0,%1,%2,%3};"
                        : "+f"(c[mt][nt][0]), "+f"(c[mt][nt][1]),
                          "+f"(c[mt][nt][2]), "+f"(c[mt][nt][3])
                        : "r"(ah[mt][0]), "r"(ah[mt][1]), "r"(ah[mt][2]), "r"(ah[mt][3]),
                          "r"(bh0), "r"(bh1));
                    asm volatile(
                        "mma.sync.aligned.m16n8k16.row.col.f32.bf16.bf16.f32 "
                        "{%0,%1,%2,%3}, {%4,%5,%6,%7}, {%8,%9}, {%0,%1,%2,%3};"
                        : "+f"(c[mt][nt][0]), "+f"(c[mt][nt][1]),
                          "+f"(c[mt][nt][2]), "+f"(c[mt][nt][3])
                        : "r"(al[mt][0]), "r"(al[mt][1]), "r"(al[mt][2]), "r"(al[mt][3]),
                          "r"(bh0), "r"(bh1));
                    asm volatile(
                        "mma.sync.aligned.m16n8k16.row.col.f32.bf16.bf16.f32 "
                        "{%0,%1,%2,%3}, {%4,%5,%6,%7}, {%8,%9}, {%0,%1,%2,%3};"
                        : "+f"(c[mt][nt][0]), "+f"(c[mt][nt][1]),
                          "+f"(c[mt][nt][2]), "+f"(c[mt][nt][3])
                        : "r"(ah[mt][0]), "r"(ah[mt][1]), "r"(ah[mt][2]), "r"(ah[mt][3]),
                          "r"(bl0), "r"(bl1));
                }
            }
        }
        __syncthreads();
    }

    // ---- Epilogue: C frags -> g_qkv fp32.
    #pragma unroll
    for (int mt = 0; mt < 2; mt++) {
        #pragma unroll
        for (int nt = 0; nt < 12; nt++) {
            int n   = wn + nt * 8;
            int mat = n >> 6;
            int h   = n & 63;
            int row = m0 + wm + mt * 16 + (lane >> 2);
            float* base = g_qkv + (size_t)mat * BT_ROWS * H_DIM +
                          (size_t)row * H_DIM + h + (lane & 3) * 2;
            *reinterpret_cast<float2*>(base) =
                make_float2(c[mt][nt][0], c[mt][nt][1]);
            *reinterpret_cast<float2*>(base + 8 * H_DIM) =
                make_float2(c[mt][nt][2], c[mt][nt][3]);
        }
    }
}

// ---------------------------------------------------------------------------
// Kernel 2: causal attention, register-blocked GEMMs. Q stored transposed
// [h][q] so the S-loop a-operand is a single LDS.128.
// ---------------------------------------------------------------------------
__global__ __launch_bounds__(256) void attn_kernel(float* __restrict__ out)
{
    __shared__ float QsT[H_DIM][64];   // [h][q]   16 KB
    __shared__ float KPs[64][64];      // K as [h][kc]; reused as P [q][k]
    __shared__ float Vs[64][H_DIM];    // [k][h]   16 KB

    const int b   = blockIdx.y;
    const int qt  = 3 - blockIdx.x;        // heavy tiles first
    const int tid = threadIdx.x;
    const int tx  = tid & 15;
    const int ty  = tid >> 4;

    const float* qp = g_qkv + (size_t)b * T_DIM * H_DIM;
    const float* kp = g_qkv + (size_t)BT_ROWS * H_DIM + (size_t)b * T_DIM * H_DIM;
    const float* vp = g_qkv + 2ull * BT_ROWS * H_DIM + (size_t)b * T_DIM * H_DIM;

    const float scale = 0.05103103630798288f;   // 384^-0.5

    #pragma unroll
    for (int r = 0; r < 4; r++) {
        int idx = tid + r * 256;
        int row = idx >> 4;
        int cg  = (idx & 15) << 2;
        float4 qv = *reinterpret_cast<const float4*>(
            &qp[(size_t)(qt * 64 + row) * H_DIM + cg]);
        QsT[cg + 0][row] = qv.x;
        QsT[cg + 1][row] = qv.y;
        QsT[cg + 2][row] = qv.z;
        QsT[cg + 3][row] = qv.w;
    }

    float acc[4][4];
    #pragma unroll
    for (int i = 0; i < 4; i++)
        #pragma unroll
        for (int j = 0; j < 4; j++) acc[i][j] = 0.f;
    float se[4] = {0.f, 0.f, 0.f, 0.f};

    for (int kt = 0; kt <= qt; kt++) {
        #pragma unroll
        for (int r = 0; r < 4; r++) {
            int idx = tid + r * 256;
            int row = idx >> 4;
            int cg  = (idx & 15) << 2;
            float4 kv = *reinterpret_cast<const float4*>(
                &kp[(size_t)(kt * 64 + row) * H_DIM + cg]);
            KPs[cg + 0][row] = kv.x;
            KPs[cg + 1][row] = kv.y;
            KPs[cg + 2][row] = kv.z;
            KPs[cg + 3][row] = kv.w;
            *reinterpret_cast<float4*>(&Vs[row][cg]) =
                *reinterpret_cast<const float4*>(
                    &vp[(size_t)(kt * 64 + row) * H_DIM + cg]);
        }
        __syncthreads();

        float p[4][4];
        #pragma unroll
        for (int i = 0; i < 4; i++)
            #pragma unroll
            for (int j = 0; j < 4; j++) p[i][j] = 0.f;

        #pragma unroll 8
        for (int hh = 0; hh < H_DIM; hh++) {
            float4 av = *reinterpret_cast<const float4*>(&QsT[hh][ty * 4]);
            float4 bv = *reinterpret_cast<const float4*>(&KPs[hh][tx * 4]);
            p[0][0] += av.x * bv.x; p[0][1] += av.x * bv.y; p[0][2] += av.x * bv.z; p[0][3] += av.x * bv.w;
            p[1][0] += av.y * bv.x; p[1][1] += av.y * bv.y; p[1][2] += av.y * bv.z; p[1][3] += av.y * bv.w;
            p[2][0] += av.z * bv.x; p[2][1] += av.z * bv.y; p[2][2] += av.z * bv.z; p[2][3] += av.z * bv.w;
            p[3][0] += av.w * bv.x; p[3][1] += av.w * bv.y; p[3][2] += av.w * bv.z; p[3][3] += av.w * bv.w;
        }

        const bool diag = (kt == qt);
        #pragma unroll
        for (int i = 0; i < 4; i++) {
            int ql = ty * 4 + i;
            #pragma unroll
            for (int j = 0; j < 4; j++) {
                int kl = tx * 4 + j;
                float e = (!diag || kl <= ql) ? __expf(p[i][j] * scale) : 0.f;
                p[i][j] = e;
                se[i] += e;
            }
        }
        __syncthreads();

        #pragma unroll
        for (int i = 0; i < 4; i++)
            *reinterpret_cast<float4*>(&KPs[ty * 4 + i][tx * 4]) =
                make_float4(p[i][0], p[i][1], p[i][2], p[i][3]);
        __syncthreads();

        #pragma unroll 8
        for (int kk = 0; kk < 64; kk++) {
            float a0 = KPs[ty * 4 + 0][kk];
            float a1 = KPs[ty * 4 + 1][kk];
            float a2 = KPs[ty * 4 + 2][kk];
            float a3 = KPs[ty * 4 + 3][kk];
            float4 bv = *reinterpret_cast<const float4*>(&Vs[kk][tx * 4]);
            acc[0][0] += a0 * bv.x; acc[0][1] += a0 * bv.y; acc[0][2] += a0 * bv.z; acc[0][3] += a0 * bv.w;
            acc[1][0] += a1 * bv.x; acc[1][1] += a1 * bv.y; acc[1][2] += a1 * bv.z; acc[1][3] += a1 * bv.w;
            acc[2][0] += a2 * bv.x; acc[2][1] += a2 * bv.y; acc[2][2] += a2 * bv.z; acc[2][3] += a2 * bv.w;
            acc[3][0] += a3 * bv.x; acc[3][1] += a3 * bv.y; acc[3][2] += a3 * bv.z; acc[3][3] += a3 * bv.w;
        }
        __syncthreads();
    }

    float* red = &QsT[0][0];
    #pragma unroll
    for (int i = 0; i < 4; i++)
        red[(ty * 4 + i) * 16 + tx] = se[i];
    __syncthreads();

    float inv[4];
    #pragma unroll
    for (int i = 0; i < 4; i++) {
        float s = 0.f;
        #pragma unroll
        for (int t = 0; t < 16; t++) s += red[(ty * 4 + i) * 16 + t];
        inv[i] = 1.f / s;
    }

    #pragma unroll
    for (int i = 0; i < 4; i++) {
        *reinterpret_cast<float4*>(
            &out[((size_t)b * T_DIM + qt * 64 + ty * 4 + i) * H_DIM + tx * 4]) =
            make_float4(acc[i][0] * inv[i], acc[i][1] * inv[i],
                        acc[i][2] * inv[i], acc[i][3] * inv[i]);
    }
}

// ---------------------------------------------------------------------------
extern "C" void kernel_launch(void* const* d_in, const int* in_sizes, int n_in,
                              void* d_out, int out_size)
{
    const float* x  = (const float*)d_in[0];
    const float* Wq = (const float*)d_in[1];
    const float* Wk = (const float*)d_in[2];
    const float* Wv = (const float*)d_in[3];
    float* out = (float*)d_out;

    wprep_kernel<<<(C_DIM * N_TOT + 255) / 256, 256>>>(Wq, Wk, Wv);
    proj_mma_kernel<<<BT_ROWS / 128, 256>>>(x);
    attn_kernel<<<dim3(4, B_DIM), 256>>>(out);
}

// round 10
// speedup vs baseline: 2.5746x; 1.2728x over previous
#include <cuda_runtime.h>
#include <cuda_bf16.h>
#include <stdint.h>

#define BT_ROWS 65536   // B*T
#define C_DIM   384
#define H_DIM   64
#define T_DIM   256
#define B_DIM   256
#define N_TOT   192     // q|k|v fused N

// fp32 q,k,v: 3 * 65536 * 64 floats = 50.3 MB
__device__ float g_qkv[3ull * BT_ROWS * H_DIM];
// Fused W in [k][n] (n = mat*64+h), bf16 hi and lo planes.
__device__ __nv_bfloat16 g_wb_hi[C_DIM * N_TOT];
__device__ __nv_bfloat16 g_wb_lo[C_DIM * N_TOT];

__device__ __forceinline__ uint32_t smem_u32(const void* p) {
    uint32_t a;
    asm("{ .reg .u64 t; cvta.to.shared.u64 t, %1; cvt.u32.u64 %0, t; }"
        : "=r"(a) : "l"(p));
    return a;
}

__device__ __forceinline__ void mma_bf16(float* c, const uint32_t* a,
                                         uint32_t b0, uint32_t b1) {
    asm volatile(
        "mma.sync.aligned.m16n8k16.row.col.f32.bf16.bf16.f32 "
        "{%0,%1,%2,%3}, {%4,%5,%6,%7}, {%8,%9}, {%0,%1,%2,%3};"
        : "+f"(c[0]), "+f"(c[1]), "+f"(c[2]), "+f"(c[3])
        : "r"(a[0]), "r"(a[1]), "r"(a[2]), "r"(a[3]), "r"(b0), "r"(b1));
}
__device__ __forceinline__ void ldm_x4(uint32_t* r, uint32_t addr) {
    asm volatile("ldmatrix.sync.aligned.m8n8.x4.shared.b16 {%0,%1,%2,%3}, [%4];"
                 : "=r"(r[0]), "=r"(r[1]), "=r"(r[2]), "=r"(r[3]) : "r"(addr));
}
__device__ __forceinline__ void ldm_x2t(uint32_t& r0, uint32_t& r1, uint32_t addr) {
    asm volatile("ldmatrix.sync.aligned.m8n8.x2.trans.shared.b16 {%0,%1}, [%2];"
                 : "=r"(r0), "=r"(r1) : "r"(addr));
}
__device__ __forceinline__ void split2(float v, unsigned short& h, unsigned short& l) {
    __nv_bfloat16 hb = __float2bfloat16(v);
    __nv_bfloat16 lb = __float2bfloat16(v - __bfloat162float(hb));
    h = reinterpret_cast<unsigned short&>(hb);
    l = reinterpret_cast<unsigned short&>(lb);
}

// ---------------------------------------------------------------------------
// Kernel 0: W -> bf16 hi/lo, fused [k][n] layout.
// ---------------------------------------------------------------------------
__global__ void wprep_kernel(const float* __restrict__ Wq,
                             const float* __restrict__ Wk,
                             const float* __restrict__ Wv)
{
    int idx = blockIdx.x * blockDim.x + threadIdx.x;
    if (idx >= C_DIM * N_TOT) return;
    int k = idx / N_TOT, n = idx % N_TOT;
    int mat = n >> 6, h = n & 63;
    const float* W = (mat == 0) ? Wq : (mat == 1) ? Wk : Wv;
    float v = W[(size_t)k * H_DIM + h];
    __nv_bfloat16 hi = __float2bfloat16(v);
    __nv_bfloat16 lo = __float2bfloat16(v - __bfloat162float(hi));
    g_wb_hi[idx] = hi;
    g_wb_lo[idx] = lo;
}

// ---------------------------------------------------------------------------
// Kernel 1: fused QKV projection via mma.sync bf16 (3-term hi/lo split).
// (unchanged from R8 passing version)
// ---------------------------------------------------------------------------
__global__ __launch_bounds__(256) void proj_mma_kernel(const float* __restrict__ x)
{
    constexpr int APAD = 40;
    constexpr int BPAD = 208;
    __shared__ __align__(16) __nv_bfloat16 Ahi[128 * APAD];
    __shared__ __align__(16) __nv_bfloat16 Alo[128 * APAD];
    __shared__ __align__(16) __nv_bfloat16 Bhi[32 * BPAD];
    __shared__ __align__(16) __nv_bfloat16 Blo[32 * BPAD];

    const int tid  = threadIdx.x;
    const int lane = tid & 31;
    const int wid  = tid >> 5;
    const int m0   = blockIdx.x * 128;
    const int wm   = (wid & 3) * 32;
    const int wn   = (wid >> 2) * 96;

    float c[2][12][4];
    #pragma unroll
    for (int mt = 0; mt < 2; mt++)
        #pragma unroll
        for (int nt = 0; nt < 12; nt++)
            #pragma unroll
            for (int r = 0; r < 4; r++) c[mt][nt][r] = 0.f;

    const uint32_t a_hi_base = smem_u32(Ahi);
    const uint32_t a_lo_base = smem_u32(Alo);
    const uint32_t b_hi_base = smem_u32(Bhi);
    const uint32_t b_lo_base = smem_u32(Blo);

    for (int kb = 0; kb < C_DIM; kb += 32) {
        #pragma unroll
        for (int r = 0; r < 4; r++) {
            int idx = tid + r * 256;
            int row = idx >> 3;
            int f4  = idx & 7;
            float4 xv = *reinterpret_cast<const float4*>(
                &x[(size_t)(m0 + row) * C_DIM + kb + f4 * 4]);
            ushort4 hs, ls;
            split2(xv.x, hs.x, ls.x);
            split2(xv.y, hs.y, ls.y);
            split2(xv.z, hs.z, ls.z);
            split2(xv.w, hs.w, ls.w);
            *reinterpret_cast<ushort4*>(&Ahi[row * APAD + f4 * 4]) = hs;
            *reinterpret_cast<ushort4*>(&Alo[row * APAD + f4 * 4]) = ls;
        }
        #pragma unroll
        for (int r = 0; r < 3; r++) {
            int idx = tid + r * 256;
            int row = idx / 24;
            int u   = idx % 24;
            uint4 sh = *reinterpret_cast<const uint4*>(
                &g_wb_hi[(size_t)(kb + row) * N_TOT + u * 8]);
            uint4 sl = *reinterpret_cast<const uint4*>(
                &g_wb_lo[(size_t)(kb + row) * N_TOT + u * 8]);
            *reinterpret_cast<uint4*>(&Bhi[row * BPAD + u * 8]) = sh;
            *reinterpret_cast<uint4*>(&Blo[row * BPAD + u * 8]) = sl;
        }
        __syncthreads();

        #pragma unroll
        for (int st = 0; st < 2; st++) {
            uint32_t ah[2][4], al[2][4];
            #pragma unroll
            for (int mt = 0; mt < 2; mt++) {
                int arow = wm + mt * 16 + (lane & 15);
                uint32_t abyte = (uint32_t)(arow * APAD + st * 16 + ((lane >> 4) << 3)) * 2;
                ldm_x4(ah[mt], a_hi_base + abyte);
                ldm_x4(al[mt], a_lo_base + abyte);
            }
            uint32_t bbyte = (uint32_t)((st * 16 + (lane & 15)) * BPAD + wn) * 2;
            #pragma unroll
            for (int nt = 0; nt < 12; nt++) {
                uint32_t bh0, bh1, bl0, bl1;
                ldm_x2t(bh0, bh1, b_hi_base + bbyte + nt * 16);
                ldm_x2t(bl0, bl1, b_lo_base + bbyte + nt * 16);
                #pragma unroll
                for (int mt = 0; mt < 2; mt++) {
                    mma_bf16(c[mt][nt], ah[mt], bh0, bh1);
                    mma_bf16(c[mt][nt], al[mt], bh0, bh1);
                    mma_bf16(c[mt][nt], ah[mt], bl0, bl1);
                }
            }
        }
        __syncthreads();
    }

    #pragma unroll
    for (int mt = 0; mt < 2; mt++) {
        #pragma unroll
        for (int nt = 0; nt < 12; nt++) {
            int n   = wn + nt * 8;
            int mat = n >> 6;
            int h   = n & 63;
            int row = m0 + wm + mt * 16 + (lane >> 2);
            float* base = g_qkv + (size_t)mat * BT_ROWS * H_DIM +
                          (size_t)row * H_DIM + h + (lane & 3) * 2;
            *reinterpret_cast<float2*>(base) =
                make_float2(c[mt][nt][0], c[mt][nt][1]);
            *reinterpret_cast<float2*>(base + 8 * H_DIM) =
                make_float2(c[mt][nt][2], c[mt][nt][3]);
        }
    }
}

// ---------------------------------------------------------------------------
// Kernel 2: causal attention on mma.sync bf16 hi/lo (3-term).
// Block = (qt, b): 64 queries. 8 warps: wm=(wid&3)*16, wn=(wid>>2)*32.
// Q frags hoisted to registers; smem buffers reused: AV = Q then V planes,
// KP = K^T then P planes. Exact single-pass softmax (bounded scores).
// ---------------------------------------------------------------------------
#define PAD 72
__global__ __launch_bounds__(256) void attn_mma_kernel(float* __restrict__ out)
{
    __shared__ __align__(16) __nv_bfloat16 AVhi[64 * PAD];  // Q then V
    __shared__ __align__(16) __nv_bfloat16 AVlo[64 * PAD];
    __shared__ __align__(16) __nv_bfloat16 KPhi[64 * PAD];  // K^T then P
    __shared__ __align__(16) __nv_bfloat16 KPlo[64 * PAD];
    __shared__ float rsum[2][64];

    const int b   = blockIdx.y;
    const int qt  = 3 - blockIdx.x;
    const int tid = threadIdx.x;
    const int lane = tid & 31;
    const int wid  = tid >> 5;
    const int wm   = (wid & 3) * 16;
    const int wn   = (wid >> 2) * 32;

    const float* qp = g_qkv + (size_t)b * T_DIM * H_DIM;
    const float* kp = g_qkv + (size_t)BT_ROWS * H_DIM + (size_t)b * T_DIM * H_DIM;
    const float* vp = g_qkv + 2ull * BT_ROWS * H_DIM + (size_t)b * T_DIM * H_DIM;
    const float scale = 0.05103103630798288f;   // 384^-0.5

    const uint32_t av_hi = smem_u32(AVhi), av_lo = smem_u32(AVlo);
    const uint32_t kp_hi = smem_u32(KPhi), kp_lo = smem_u32(KPlo);

    // ---- Stage Q tile [64 x 64] as hi/lo planes.
    #pragma unroll
    for (int r = 0; r < 4; r++) {
        int idx = tid + r * 256;
        int row = idx >> 4;
        int cg  = (idx & 15) << 2;
        float4 qv = *reinterpret_cast<const float4*>(
            &qp[(size_t)(qt * 64 + row) * H_DIM + cg]);
        ushort4 hs, ls;
        split2(qv.x, hs.x, ls.x);
        split2(qv.y, hs.y, ls.y);
        split2(qv.z, hs.z, ls.z);
        split2(qv.w, hs.w, ls.w);
        *reinterpret_cast<ushort4*>(&AVhi[row * PAD + cg]) = hs;
        *reinterpret_cast<ushort4*>(&AVlo[row * PAD + cg]) = ls;
    }
    __syncthreads();

    // ---- Hoist Q fragments (constant across key tiles): 4 k-steps.
    uint32_t qh[4][4], ql[4][4];
    #pragma unroll
    for (int st = 0; st < 4; st++) {
        uint32_t abyte = (uint32_t)((wm + (lane & 15)) * PAD + st * 16 + ((lane >> 4) << 3)) * 2;
        ldm_x4(qh[st], av_hi + abyte);
        ldm_x4(ql[st], av_lo + abyte);
    }

    float o[4][4];
    #pragma unroll
    for (int nt = 0; nt < 4; nt++)
        #pragma unroll
        for (int r = 0; r < 4; r++) o[nt][r] = 0.f;
    float rs0 = 0.f, rs1 = 0.f;   // row partial sums (rows lane>>2, +8)

    for (int kt = 0; kt <= qt; kt++) {
        __syncthreads();   // prior iter done reading AV (V) and KP (P)

        // ---- Stage K^T (into KP) and V (into AV) hi/lo planes.
        #pragma unroll
        for (int r = 0; r < 4; r++) {
            int idx = tid + r * 256;
            int row = idx >> 4;               // key index 0..63
            int cg  = (idx & 15) << 2;        // h group
            float4 kv = *reinterpret_cast<const float4*>(
                &kp[(size_t)(kt * 64 + row) * H_DIM + cg]);
            float4 vv = *reinterpret_cast<const float4*>(
                &vp[(size_t)(kt * 64 + row) * H_DIM + cg]);
            unsigned short h0, l0;
            split2(kv.x, h0, l0); KPhi[(cg + 0) * PAD + row] = reinterpret_cast<__nv_bfloat16&>(h0);
                                  KPlo[(cg + 0) * PAD + row] = reinterpret_cast<__nv_bfloat16&>(l0);
            split2(kv.y, h0, l0); KPhi[(cg + 1) * PAD + row] = reinterpret_cast<__nv_bfloat16&>(h0);
                                  KPlo[(cg + 1) * PAD + row] = reinterpret_cast<__nv_bfloat16&>(l0);
            split2(kv.z, h0, l0); KPhi[(cg + 2) * PAD + row] = reinterpret_cast<__nv_bfloat16&>(h0);
                                  KPlo[(cg + 2) * PAD + row] = reinterpret_cast<__nv_bfloat16&>(l0);
            split2(kv.w, h0, l0); KPhi[(cg + 3) * PAD + row] = reinterpret_cast<__nv_bfloat16&>(h0);
                                  KPlo[(cg + 3) * PAD + row] = reinterpret_cast<__nv_bfloat16&>(l0);
            ushort4 hs, ls;
            split2(vv.x, hs.x, ls.x);
            split2(vv.y, hs.y, ls.y);
            split2(vv.z, hs.z, ls.z);
            split2(vv.w, hs.w, ls.w);
            *reinterpret_cast<ushort4*>(&AVhi[row * PAD + cg]) = hs;
            *reinterpret_cast<ushort4*>(&AVlo[row * PAD + cg]) = ls;
        }
        __syncthreads();

        // ---- S = Q K^T (3-term). KP holds K^T as [h][key].
        float s[4][4];
        #pragma unroll
        for (int nt = 0; nt < 4; nt++)
            #pragma unroll
            for (int r = 0; r < 4; r++) s[nt][r] = 0.f;

        #pragma unroll
        for (int st = 0; st < 4; st++) {
            uint32_t bbyte = (uint32_t)((st * 16 + (lane & 15)) * PAD + wn) * 2;
            #pragma unroll
            for (int nt = 0; nt < 4; nt++) {
                uint32_t bh0, bh1, bl0, bl1;
                ldm_x2t(bh0, bh1, kp_hi + bbyte + nt * 16);
                ldm_x2t(bl0, bl1, kp_lo + bbyte + nt * 16);
                mma_bf16(s[nt], qh[st], bh0, bh1);
                mma_bf16(s[nt], ql[st], bh0, bh1);
                mma_bf16(s[nt], qh[st], bl0, bl1);
            }
        }

        // ---- exp + causal mask in fragments; accumulate row sums.
        const bool diag = (kt == qt);
        const int rlo = (lane >> 2), rhi = rlo + 8;
        #pragma unroll
        for (int nt = 0; nt < 4; nt++) {
            int c0 = wn + nt * 8 + (lane & 3) * 2;
            float e0 = (!diag || c0     <= wm + rlo) ? __expf(s[nt][0] * scale) : 0.f;
            float e1 = (!diag || c0 + 1 <= wm + rlo) ? __expf(s[nt][1] * scale) : 0.f;
            float e2 = (!diag || c0     <= wm + rhi) ? __expf(s[nt][2] * scale) : 0.f;
            float e3 = (!diag || c0 + 1 <= wm + rhi) ? __expf(s[nt][3] * scale) : 0.f;
            s[nt][0] = e0; s[nt][1] = e1; s[nt][2] = e2; s[nt][3] = e3;
            rs0 += e0 + e1;
            rs1 += e2 + e3;
        }
        __syncthreads();   // all warps done reading K^T from KP

        // ---- Stage P hi/lo into KP as [q][kc] (pairs of cols -> b32).
        #pragma unroll
        for (int nt = 0; nt < 4; nt++) {
            int pcol = wn + nt * 8 + (lane & 3) * 2;
            unsigned short h0, l0, h1, l1;
            split2(s[nt][0], h0, l0);
            split2(s[nt][1], h1, l1);
            *reinterpret_cast<uint32_t*>(&KPhi[(wm + rlo) * PAD + pcol]) =
                (uint32_t)h0 | ((uint32_t)h1 << 16);
            *reinterpret_cast<uint32_t*>(&KPlo[(wm + rlo) * PAD + pcol]) =
                (uint32_t)l0 | ((uint32_t)l1 << 16);
            split2(s[nt][2], h0, l0);
            split2(s[nt][3], h1, l1);
            *reinterpret_cast<uint32_t*>(&KPhi[(wm + rhi) * PAD + pcol]) =
                (uint32_t)h0 | ((uint32_t)h1 << 16);
            *reinterpret_cast<uint32_t*>(&KPlo[(wm + rhi) * PAD + pcol]) =
                (uint32_t)l0 | ((uint32_t)l1 << 16);
        }
        __syncthreads();

        // ---- O += P V (3-term). P in KP [q][kc], V in AV [kc][h].
        #pragma unroll
        for (int st = 0; st < 4; st++) {
            uint32_t ph[4], pl[4];
            uint32_t abyte = (uint32_t)((wm + (lane & 15)) * PAD + st * 16 + ((lane >> 4) << 3)) * 2;
            ldm_x4(ph, kp_hi + abyte);
            ldm_x4(pl, kp_lo + abyte);
            uint32_t bbyte = (uint32_t)((st * 16 + (lane & 15)) * PAD + wn) * 2;
            #pragma unroll
            for (int nt = 0; nt < 4; nt++) {
                uint32_t bh0, bh1, bl0, bl1;
                ldm_x2t(bh0, bh1, av_hi + bbyte + nt * 16);
                ldm_x2t(bl0, bl1, av_lo + bbyte + nt * 16);
                mma_bf16(o[nt], ph, bh0, bh1);
                mma_bf16(o[nt], pl, bh0, bh1);
                mma_bf16(o[nt], ph, bl0, bl1);
            }
        }
    }

    // ---- Reduce row sums: across the 4 lanes sharing a row, then across
    // the 2 n-warp groups via smem.
    rs0 += __shfl_xor_sync(0xFFFFFFFF, rs0, 1);
    rs0 += __shfl_xor_sync(0xFFFFFFFF, rs0, 2);
    rs1 += __shfl_xor_sync(0xFFFFFFFF, rs1, 1);
    rs1 += __shfl_xor_sync(0xFFFFFFFF, rs1, 2);
    if ((lane & 3) == 0) {
        rsum[wid >> 2][wm + (lane >> 2)]     = rs0;
        rsum[wid >> 2][wm + (lane >> 2) + 8] = rs1;
    }
    __syncthreads();

    const float inv0 = 1.f / (rsum[0][wm + (lane >> 2)]     + rsum[1][wm + (lane >> 2)]);
    const float inv1 = 1.f / (rsum[0][wm + (lane >> 2) + 8] + rsum[1][wm + (lane >> 2) + 8]);

    // ---- Store O.
    const int qrow0 = qt * 64 + wm + (lane >> 2);
    #pragma unroll
    for (int nt = 0; nt < 4; nt++) {
        int col = wn + nt * 8 + (lane & 3) * 2;
        *reinterpret_cast<float2*>(
            &out[((size_t)b * T_DIM + qrow0) * H_DIM + col]) =
            make_float2(o[nt][0] * inv0, o[nt][1] * inv0);
        *reinterpret_cast<float2*>(
            &out[((size_t)b * T_DIM + qrow0 + 8) * H_DIM + col]) =
            make_float2(o[nt][2] * inv1, o[nt][3] * inv1);
    }
}

// ---------------------------------------------------------------------------
extern "C" void kernel_launch(void* const* d_in, const int* in_sizes, int n_in,
                              void* d_out, int out_size)
{
    const float* x  = (const float*)d_in[0];
    const float* Wq = (const float*)d_in[1];
    const float* Wk = (const float*)d_in[2];
    const float* Wv = (const float*)d_in[3];
    float* out = (float*)d_out;

    wprep_kernel<<<(C_DIM * N_TOT + 255) / 256, 256>>>(Wq, Wk, Wv);
    proj_mma_kernel<<<BT_ROWS / 128, 256>>>(x);
    attn_mma_kernel<<<dim3(4, B_DIM), 256>>>(out);
}

// round 11
// speedup vs baseline: 2.7857x; 1.0820x over previous
#include <cuda_runtime.h>
#include <cuda_bf16.h>
#include <stdint.h>

#define BT_ROWS 65536   // B*T
#define C_DIM   384
#define H_DIM   64
#define T_DIM   256
#define B_DIM   256
#define N_TOT   192     // q|k|v fused N

// fp32 q,k,v: 3 * 65536 * 64 floats = 50.3 MB
__device__ float g_qkv[3ull * BT_ROWS * H_DIM];
// Fused W in [k][n] (n = mat*64+h), bf16 hi and lo planes.
__device__ __nv_bfloat16 g_wb_hi[C_DIM * N_TOT];
__device__ __nv_bfloat16 g_wb_lo[C_DIM * N_TOT];

__device__ __forceinline__ uint32_t smem_u32(const void* p) {
    uint32_t a;
    asm("{ .reg .u64 t; cvta.to.shared.u64 t, %1; cvt.u32.u64 %0, t; }"
        : "=r"(a) : "l"(p));
    return a;
}

__device__ __forceinline__ void mma_bf16(float* c, const uint32_t* a,
                                         uint32_t b0, uint32_t b1) {
    asm volatile(
        "mma.sync.aligned.m16n8k16.row.col.f32.bf16.bf16.f32 "
        "{%0,%1,%2,%3}, {%4,%5,%6,%7}, {%8,%9}, {%0,%1,%2,%3};"
        : "+f"(c[0]), "+f"(c[1]), "+f"(c[2]), "+f"(c[3])
        : "r"(a[0]), "r"(a[1]), "r"(a[2]), "r"(a[3]), "r"(b0), "r"(b1));
}
__device__ __forceinline__ void ldm_x4(uint32_t* r, uint32_t addr) {
    asm volatile("ldmatrix.sync.aligned.m8n8.x4.shared.b16 {%0,%1,%2,%3}, [%4];"
                 : "=r"(r[0]), "=r"(r[1]), "=r"(r[2]), "=r"(r[3]) : "r"(addr));
}
__device__ __forceinline__ void ldm_x2t(uint32_t& r0, uint32_t& r1, uint32_t addr) {
    asm volatile("ldmatrix.sync.aligned.m8n8.x2.trans.shared.b16 {%0,%1}, [%2];"
                 : "=r"(r0), "=r"(r1) : "r"(addr));
}
__device__ __forceinline__ void split2(float v, unsigned short& h, unsigned short& l) {
    __nv_bfloat16 hb = __float2bfloat16(v);
    __nv_bfloat16 lb = __float2bfloat16(v - __bfloat162float(hb));
    h = reinterpret_cast<unsigned short&>(hb);
    l = reinterpret_cast<unsigned short&>(lb);
}

// ---------------------------------------------------------------------------
// Kernel 0: W -> bf16 hi/lo, fused [k][n] layout.
// ---------------------------------------------------------------------------
__global__ void wprep_kernel(const float* __restrict__ Wq,
                             const float* __restrict__ Wk,
                             const float* __restrict__ Wv)
{
    int idx = blockIdx.x * blockDim.x + threadIdx.x;
    if (idx >= C_DIM * N_TOT) return;
    int k = idx / N_TOT, n = idx % N_TOT;
    int mat = n >> 6, h = n & 63;
    const float* W = (mat == 0) ? Wq : (mat == 1) ? Wk : Wv;
    float v = W[(size_t)k * H_DIM + h];
    __nv_bfloat16 hi = __float2bfloat16(v);
    __nv_bfloat16 lo = __float2bfloat16(v - __bfloat162float(hi));
    g_wb_hi[idx] = hi;
    g_wb_lo[idx] = lo;
}

// ---------------------------------------------------------------------------
// Kernel 1: fused QKV projection via mma.sync bf16 (3-term hi/lo split),
// register-prefetch pipelined: chunk c+1's LDGs issue right after the sync
// that precedes chunk c's MMA phase, hiding DRAM latency under the HMMAs.
// ---------------------------------------------------------------------------
__global__ __launch_bounds__(256) void proj_mma_kernel(const float* __restrict__ x)
{
    constexpr int APAD = 40;
    constexpr int BPAD = 208;
    __shared__ __align__(16) __nv_bfloat16 Ahi[128 * APAD];
    __shared__ __align__(16) __nv_bfloat16 Alo[128 * APAD];
    __shared__ __align__(16) __nv_bfloat16 Bhi[32 * BPAD];
    __shared__ __align__(16) __nv_bfloat16 Blo[32 * BPAD];

    const int tid  = threadIdx.x;
    const int lane = tid & 31;
    const int wid  = tid >> 5;
    const int m0   = blockIdx.x * 128;
    const int wm   = (wid & 3) * 32;
    const int wn   = (wid >> 2) * 96;

    // Per-thread fixed staging coordinates.
    int xrow[4], xf4[4];
    #pragma unroll
    for (int r = 0; r < 4; r++) {
        int idx = tid + r * 256;
        xrow[r] = idx >> 3;
        xf4[r]  = idx & 7;
    }
    int wrow[3], wu[3];
    #pragma unroll
    for (int r = 0; r < 3; r++) {
        int idx = tid + r * 256;
        wrow[r] = idx / 24;
        wu[r]   = idx % 24;
    }

    float c[2][12][4];
    #pragma unroll
    for (int mt = 0; mt < 2; mt++)
        #pragma unroll
        for (int nt = 0; nt < 12; nt++)
            #pragma unroll
            for (int r = 0; r < 4; r++) c[mt][nt][r] = 0.f;

    const uint32_t a_hi_base = smem_u32(Ahi);
    const uint32_t a_lo_base = smem_u32(Alo);
    const uint32_t b_hi_base = smem_u32(Bhi);
    const uint32_t b_lo_base = smem_u32(Blo);

    // ---- Prologue: prefetch chunk 0 into registers.
    float4 xr[4];
    uint4  wh[3], wl[3];
    #pragma unroll
    for (int r = 0; r < 4; r++)
        xr[r] = *reinterpret_cast<const float4*>(
            &x[(size_t)(m0 + xrow[r]) * C_DIM + 0 + xf4[r] * 4]);
    #pragma unroll
    for (int r = 0; r < 3; r++) {
        wh[r] = *reinterpret_cast<const uint4*>(
            &g_wb_hi[(size_t)(0 + wrow[r]) * N_TOT + wu[r] * 8]);
        wl[r] = *reinterpret_cast<const uint4*>(
            &g_wb_lo[(size_t)(0 + wrow[r]) * N_TOT + wu[r] * 8]);
    }

    for (int cchunk = 0; cchunk < C_DIM / 32; cchunk++) {
        // ---- cvt + STS from prefetched registers.
        #pragma unroll
        for (int r = 0; r < 4; r++) {
            ushort4 hs, ls;
            split2(xr[r].x, hs.x, ls.x);
            split2(xr[r].y, hs.y, ls.y);
            split2(xr[r].z, hs.z, ls.z);
            split2(xr[r].w, hs.w, ls.w);
            *reinterpret_cast<ushort4*>(&Ahi[xrow[r] * APAD + xf4[r] * 4]) = hs;
            *reinterpret_cast<ushort4*>(&Alo[xrow[r] * APAD + xf4[r] * 4]) = ls;
        }
        #pragma unroll
        for (int r = 0; r < 3; r++) {
            *reinterpret_cast<uint4*>(&Bhi[wrow[r] * BPAD + wu[r] * 8]) = wh[r];
            *reinterpret_cast<uint4*>(&Blo[wrow[r] * BPAD + wu[r] * 8]) = wl[r];
        }
        __syncthreads();

        // ---- Issue next chunk's LDGs (latency hidden under MMA phase).
        if (cchunk + 1 < C_DIM / 32) {
            const int kb = (cchunk + 1) * 32;
            #pragma unroll
            for (int r = 0; r < 4; r++)
                xr[r] = *reinterpret_cast<const float4*>(
                    &x[(size_t)(m0 + xrow[r]) * C_DIM + kb + xf4[r] * 4]);
            #pragma unroll
            for (int r = 0; r < 3; r++) {
                wh[r] = *reinterpret_cast<const uint4*>(
                    &g_wb_hi[(size_t)(kb + wrow[r]) * N_TOT + wu[r] * 8]);
                wl[r] = *reinterpret_cast<const uint4*>(
                    &g_wb_lo[(size_t)(kb + wrow[r]) * N_TOT + wu[r] * 8]);
            }
        }

        // ---- MMA phase: 2 k16-steps.
        #pragma unroll
        for (int st = 0; st < 2; st++) {
            uint32_t ah[2][4], al[2][4];
            #pragma unroll
            for (int mt = 0; mt < 2; mt++) {
                int arow = wm + mt * 16 + (lane & 15);
                uint32_t abyte = (uint32_t)(arow * APAD + st * 16 + ((lane >> 4) << 3)) * 2;
                ldm_x4(ah[mt], a_hi_base + abyte);
                ldm_x4(al[mt], a_lo_base + abyte);
            }
            uint32_t bbyte = (uint32_t)((st * 16 + (lane & 15)) * BPAD + wn) * 2;
            #pragma unroll
            for (int nt = 0; nt < 12; nt++) {
                uint32_t bh0, bh1, bl0, bl1;
                ldm_x2t(bh0, bh1, b_hi_base + bbyte + nt * 16);
                ldm_x2t(bl0, bl1, b_lo_base + bbyte + nt * 16);
                #pragma unroll
                for (int mt = 0; mt < 2; mt++) {
                    mma_bf16(c[mt][nt], ah[mt], bh0, bh1);
                    mma_bf16(c[mt][nt], al[mt], bh0, bh1);
                    mma_bf16(c[mt][nt], ah[mt], bl0, bl1);
                }
            }
        }
        __syncthreads();
    }

    #pragma unroll
    for (int mt = 0; mt < 2; mt++) {
        #pragma unroll
        for (int nt = 0; nt < 12; nt++) {
            int n   = wn + nt * 8;
            int mat = n >> 6;
            int h   = n & 63;
            int row = m0 + wm + mt * 16 + (lane >> 2);
            float* base = g_qkv + (size_t)mat * BT_ROWS * H_DIM +
                          (size_t)row * H_DIM + h + (lane & 3) * 2;
            *reinterpret_cast<float2*>(base) =
                make_float2(c[mt][nt][0], c[mt][nt][1]);
            *reinterpret_cast<float2*>(base + 8 * H_DIM) =
                make_float2(c[mt][nt][2], c[mt][nt][3]);
        }
    }
}

// ---------------------------------------------------------------------------
// Kernel 2: causal attention on mma.sync bf16 hi/lo (3-term).
// (unchanged from R10 passing version)
// ---------------------------------------------------------------------------
#define PAD 72
__global__ __launch_bounds__(256) void attn_mma_kernel(float* __restrict__ out)
{
    __shared__ __align__(16) __nv_bfloat16 AVhi[64 * PAD];  // Q then V
    __shared__ __align__(16) __nv_bfloat16 AVlo[64 * PAD];
    __shared__ __align__(16) __nv_bfloat16 KPhi[64 * PAD];  // K^T then P
    __shared__ __align__(16) __nv_bfloat16 KPlo[64 * PAD];
    __shared__ float rsum[2][64];

    const int b   = blockIdx.y;
    const int qt  = 3 - blockIdx.x;
    const int tid = threadIdx.x;
    const int lane = tid & 31;
    const int wid  = tid >> 5;
    const int wm   = (wid & 3) * 16;
    const int wn   = (wid >> 2) * 32;

    const float* qp = g_qkv + (size_t)b * T_DIM * H_DIM;
    const float* kp = g_qkv + (size_t)BT_ROWS * H_DIM + (size_t)b * T_DIM * H_DIM;
    const float* vp = g_qkv + 2ull * BT_ROWS * H_DIM + (size_t)b * T_DIM * H_DIM;
    const float scale = 0.05103103630798288f;   // 384^-0.5

    const uint32_t av_hi = smem_u32(AVhi), av_lo = smem_u32(AVlo);
    const uint32_t kp_hi = smem_u32(KPhi), kp_lo = smem_u32(KPlo);

    // ---- Stage Q tile [64 x 64] as hi/lo planes.
    #pragma unroll
    for (int r = 0; r < 4; r++) {
        int idx = tid + r * 256;
        int row = idx >> 4;
        int cg  = (idx & 15) << 2;
        float4 qv = *reinterpret_cast<const float4*>(
            &qp[(size_t)(qt * 64 + row) * H_DIM + cg]);
        ushort4 hs, ls;
        split2(qv.x, hs.x, ls.x);
        split2(qv.y, hs.y, ls.y);
        split2(qv.z, hs.z, ls.z);
        split2(qv.w, hs.w, ls.w);
        *reinterpret_cast<ushort4*>(&AVhi[row * PAD + cg]) = hs;
        *reinterpret_cast<ushort4*>(&AVlo[row * PAD + cg]) = ls;
    }
    __syncthreads();

    // ---- Hoist Q fragments (constant across key tiles): 4 k-steps.
    uint32_t qh[4][4], ql[4][4];
    #pragma unroll
    for (int st = 0; st < 4; st++) {
        uint32_t abyte = (uint32_t)((wm + (lane & 15)) * PAD + st * 16 + ((lane >> 4) << 3)) * 2;
        ldm_x4(qh[st], av_hi + abyte);
        ldm_x4(ql[st], av_lo + abyte);
    }

    float o[4][4];
    #pragma unroll
    for (int nt = 0; nt < 4; nt++)
        #pragma unroll
        for (int r = 0; r < 4; r++) o[nt][r] = 0.f;
    float rs0 = 0.f, rs1 = 0.f;   // row partial sums (rows lane>>2, +8)

    for (int kt = 0; kt <= qt; kt++) {
        __syncthreads();   // prior iter done reading AV (V) and KP (P)

        // ---- Stage K^T (into KP) and V (into AV) hi/lo planes.
        #pragma unroll
        for (int r = 0; r < 4; r++) {
            int idx = tid + r * 256;
            int row = idx >> 4;               // key index 0..63
            int cg  = (idx & 15) << 2;        // h group
            float4 kv = *reinterpret_cast<const float4*>(
                &kp[(size_t)(kt * 64 + row) * H_DIM + cg]);
            float4 vv = *reinterpret_cast<const float4*>(
                &vp[(size_t)(kt * 64 + row) * H_DIM + cg]);
            unsigned short h0, l0;
            split2(kv.x, h0, l0); KPhi[(cg + 0) * PAD + row] = reinterpret_cast<__nv_bfloat16&>(h0);
                                  KPlo[(cg + 0) * PAD + row] = reinterpret_cast<__nv_bfloat16&>(l0);
            split2(kv.y, h0, l0); KPhi[(cg + 1) * PAD + row] = reinterpret_cast<__nv_bfloat16&>(h0);
                                  KPlo[(cg + 1) * PAD + row] = reinterpret_cast<__nv_bfloat16&>(l0);
            split2(kv.z, h0, l0); KPhi[(cg + 2) * PAD + row] = reinterpret_cast<__nv_bfloat16&>(h0);
                                  KPlo[(cg + 2) * PAD + row] = reinterpret_cast<__nv_bfloat16&>(l0);
            split2(kv.w, h0, l0); KPhi[(cg + 3) * PAD + row] = reinterpret_cast<__nv_bfloat16&>(h0);
                                  KPlo[(cg + 3) * PAD + row] = reinterpret_cast<__nv_bfloat16&>(l0);
            ushort4 hs, ls;
            split2(vv.x, hs.x, ls.x);
            split2(vv.y, hs.y, ls.y);
            split2(vv.z, hs.z, ls.z);
            split2(vv.w, hs.w, ls.w);
            *reinterpret_cast<ushort4*>(&AVhi[row * PAD + cg]) = hs;
            *reinterpret_cast<ushort4*>(&AVlo[row * PAD + cg]) = ls;
        }
        __syncthreads();

        // ---- S = Q K^T (3-term). KP holds K^T as [h][key].
        float s[4][4];
        #pragma unroll
        for (int nt = 0; nt < 4; nt++)
            #pragma unroll
            for (int r = 0; r < 4; r++) s[nt][r] = 0.f;

        #pragma unroll
        for (int st = 0; st < 4; st++) {
            uint32_t bbyte = (uint32_t)((st * 16 + (lane & 15)) * PAD + wn) * 2;
            #pragma unroll
            for (int nt = 0; nt < 4; nt++) {
                uint32_t bh0, bh1, bl0, bl1;
                ldm_x2t(bh0, bh1, kp_hi + bbyte + nt * 16);
                ldm_x2t(bl0, bl1, kp_lo + bbyte + nt * 16);
                mma_bf16(s[nt], qh[st], bh0, bh1);
                mma_bf16(s[nt], ql[st], bh0, bh1);
                mma_bf16(s[nt], qh[st], bl0, bl1);
            }
        }

        // ---- exp + causal mask in fragments; accumulate row sums.
        const bool diag = (kt == qt);
        const int rlo = (lane >> 2), rhi = rlo + 8;
        #pragma unroll
        for (int nt = 0; nt < 4; nt++) {
            int c0 = wn + nt * 8 + (lane & 3) * 2;
            float e0 = (!diag || c0     <= wm + rlo) ? __expf(s[nt][0] * scale) : 0.f;
            float e1 = (!diag || c0 + 1 <= wm + rlo) ? __expf(s[nt][1] * scale) : 0.f;
            float e2 = (!diag || c0     <= wm + rhi) ? __expf(s[nt][2] * scale) : 0.f;
            float e3 = (!diag || c0 + 1 <= wm + rhi) ? __expf(s[nt][3] * scale) : 0.f;
            s[nt][0] = e0; s[nt][1] = e1; s[nt][2] = e2; s[nt][3] = e3;
            rs0 += e0 + e1;
            rs1 += e2 + e3;
        }
        __syncthreads();   // all warps done reading K^T from KP

        // ---- Stage P hi/lo into KP as [q][kc] (pairs of cols -> b32).
        #pragma unroll
        for (int nt = 0; nt < 4; nt++) {
            int pcol = wn + nt * 8 + (lane & 3) * 2;
            unsigned short h0, l0, h1, l1;
            split2(s[nt][0], h0, l0);
            split2(s[nt][1], h1, l1);
            *reinterpret_cast<uint32_t*>(&KPhi[(wm + rlo) * PAD + pcol]) =
                (uint32_t)h0 | ((uint32_t)h1 << 16);
            *reinterpret_cast<uint32_t*>(&KPlo[(wm + rlo) * PAD + pcol]) =
                (uint32_t)l0 | ((uint32_t)l1 << 16);
            split2(s[nt][2], h0, l0);
            split2(s[nt][3], h1, l1);
            *reinterpret_cast<uint32_t*>(&KPhi[(wm + rhi) * PAD + pcol]) =
                (uint32_t)h0 | ((uint32_t)h1 << 16);
            *reinterpret_cast<uint32_t*>(&KPlo[(wm + rhi) * PAD + pcol]) =
                (uint32_t)l0 | ((uint32_t)l1 << 16);
        }
        __syncthreads();

        // ---- O += P V (3-term). P in KP [q][kc], V in AV [kc][h].
        #pragma unroll
        for (int st = 0; st < 4; st++) {
            uint32_t ph[4], pl[4];
            uint32_t abyte = (uint32_t)((wm + (lane & 15)) * PAD + st * 16 + ((lane >> 4) << 3)) * 2;
            ldm_x4(ph, kp_hi + abyte);
            ldm_x4(pl, kp_lo + abyte);
            uint32_t bbyte = (uint32_t)((st * 16 + (lane & 15)) * PAD + wn) * 2;
            #pragma unroll
            for (int nt = 0; nt < 4; nt++) {
                uint32_t bh0, bh1, bl0, bl1;
                ldm_x2t(bh0, bh1, av_hi + bbyte + nt * 16);
                ldm_x2t(bl0, bl1, av_lo + bbyte + nt * 16);
                mma_bf16(o[nt], ph, bh0, bh1);
                mma_bf16(o[nt], pl, bh0, bh1);
                mma_bf16(o[nt], ph, bl0, bl1);
            }
        }
    }

    // ---- Reduce row sums: across the 4 lanes sharing a row, then across
    // the 2 n-warp groups via smem.
    rs0 += __shfl_xor_sync(0xFFFFFFFF, rs0, 1);
    rs0 += __shfl_xor_sync(0xFFFFFFFF, rs0, 2);
    rs1 += __shfl_xor_sync(0xFFFFFFFF, rs1, 1);
    rs1 += __shfl_xor_sync(0xFFFFFFFF, rs1, 2);
    if ((lane & 3) == 0) {
        rsum[wid >> 2][wm + (lane >> 2)]     = rs0;
        rsum[wid >> 2][wm + (lane >> 2) + 8] = rs1;
    }
    __syncthreads();

    const float inv0 = 1.f / (rsum[0][wm + (lane >> 2)]     + rsum[1][wm + (lane >> 2)]);
    const float inv1 = 1.f / (rsum[0][wm + (lane >> 2) + 8] + rsum[1][wm + (lane >> 2) + 8]);

    // ---- Store O.
    const int qrow0 = qt * 64 + wm + (lane >> 2);
    #pragma unroll
    for (int nt = 0; nt < 4; nt++) {
        int col = wn + nt * 8 + (lane & 3) * 2;
        *reinterpret_cast<float2*>(
            &out[((size_t)b * T_DIM + qrow0) * H_DIM + col]) =
            make_float2(o[nt][0] * inv0, o[nt][1] * inv0);
        *reinterpret_cast<float2*>(
            &out[((size_t)b * T_DIM + qrow0 + 8) * H_DIM + col]) =
            make_float2(o[nt][2] * inv1, o[nt][3] * inv1);
    }
}

// ---------------------------------------------------------------------------
extern "C" void kernel_launch(void* const* d_in, const int* in_sizes, int n_in,
                              void* d_out, int out_size)
{
    const float* x  = (const float*)d_in[0];
    const float* Wq = (const float*)d_in[1];
    const float* Wk = (const float*)d_in[2];
    const float* Wv = (const float*)d_in[3];
    float* out = (float*)d_out;

    wprep_kernel<<<(C_DIM * N_TOT + 255) / 256, 256>>>(Wq, Wk, Wv);
    proj_mma_kernel<<<BT_ROWS / 128, 256>>>(x);
    attn_mma_kernel<<<dim3(4, B_DIM), 256>>>(out);
}

// round 12
// speedup vs baseline: 2.8820x; 1.0346x over previous
#include <cuda_runtime.h>
#include <cuda_bf16.h>
#include <stdint.h>

#define BT_ROWS 65536   // B*T
#define C_DIM   384
#define H_DIM   64
#define T_DIM   256
#define B_DIM   256
#define N_TOT   192     // q|k|v fused N

// q,k,v as bf16 hi/lo planes, [row][h] layout (row = b*T + t). 6 x 8.4 MB.
__device__ __nv_bfloat16 g_q_hi[(size_t)BT_ROWS * H_DIM];
__device__ __nv_bfloat16 g_q_lo[(size_t)BT_ROWS * H_DIM];
__device__ __nv_bfloat16 g_k_hi[(size_t)BT_ROWS * H_DIM];
__device__ __nv_bfloat16 g_k_lo[(size_t)BT_ROWS * H_DIM];
__device__ __nv_bfloat16 g_v_hi[(size_t)BT_ROWS * H_DIM];
__device__ __nv_bfloat16 g_v_lo[(size_t)BT_ROWS * H_DIM];
// Fused W in [k][n] (n = mat*64+h), bf16 hi and lo planes.
__device__ __nv_bfloat16 g_wb_hi[C_DIM * N_TOT];
__device__ __nv_bfloat16 g_wb_lo[C_DIM * N_TOT];

__device__ __forceinline__ uint32_t smem_u32(const void* p) {
    uint32_t a;
    asm("{ .reg .u64 t; cvta.to.shared.u64 t, %1; cvt.u32.u64 %0, t; }"
        : "=r"(a) : "l"(p));
    return a;
}
__device__ __forceinline__ void mma_bf16(float* c, const uint32_t* a,
                                         uint32_t b0, uint32_t b1) {
    asm volatile(
        "mma.sync.aligned.m16n8k16.row.col.f32.bf16.bf16.f32 "
        "{%0,%1,%2,%3}, {%4,%5,%6,%7}, {%8,%9}, {%0,%1,%2,%3};"
        : "+f"(c[0]), "+f"(c[1]), "+f"(c[2]), "+f"(c[3])
        : "r"(a[0]), "r"(a[1]), "r"(a[2]), "r"(a[3]), "r"(b0), "r"(b1));
}
__device__ __forceinline__ void ldm_x4(uint32_t* r, uint32_t addr) {
    asm volatile("ldmatrix.sync.aligned.m8n8.x4.shared.b16 {%0,%1,%2,%3}, [%4];"
                 : "=r"(r[0]), "=r"(r[1]), "=r"(r[2]), "=r"(r[3]) : "r"(addr));
}
__device__ __forceinline__ void ldm_x2t(uint32_t& r0, uint32_t& r1, uint32_t addr) {
    asm volatile("ldmatrix.sync.aligned.m8n8.x2.trans.shared.b16 {%0,%1}, [%2];"
                 : "=r"(r0), "=r"(r1) : "r"(addr));
}
__device__ __forceinline__ void ldm_x2(uint32_t& r0, uint32_t& r1, uint32_t addr) {
    asm volatile("ldmatrix.sync.aligned.m8n8.x2.shared.b16 {%0,%1}, [%2];"
                 : "=r"(r0), "=r"(r1) : "r"(addr));
}
__device__ __forceinline__ void split2(float v, unsigned short& h, unsigned short& l) {
    __nv_bfloat16 hb = __float2bfloat16(v);
    __nv_bfloat16 lb = __float2bfloat16(v - __bfloat162float(hb));
    h = reinterpret_cast<unsigned short&>(hb);
    l = reinterpret_cast<unsigned short&>(lb);
}

// ---------------------------------------------------------------------------
// Kernel 0: W -> bf16 hi/lo, fused [k][n] layout.
// ---------------------------------------------------------------------------
__global__ void wprep_kernel(const float* __restrict__ Wq,
                             const float* __restrict__ Wk,
                             const float* __restrict__ Wv)
{
    int idx = blockIdx.x * blockDim.x + threadIdx.x;
    if (idx >= C_DIM * N_TOT) return;
    int k = idx / N_TOT, n = idx % N_TOT;
    int mat = n >> 6, h = n & 63;
    const float* W = (mat == 0) ? Wq : (mat == 1) ? Wk : Wv;
    float v = W[(size_t)k * H_DIM + h];
    __nv_bfloat16 hi = __float2bfloat16(v);
    __nv_bfloat16 lo = __float2bfloat16(v - __bfloat162float(hi));
    g_wb_hi[idx] = hi;
    g_wb_lo[idx] = lo;
}

// ---------------------------------------------------------------------------
// Kernel 1: fused QKV projection via mma.sync bf16 (3-term hi/lo split),
// register-prefetch pipelined. Epilogue stores q/k/v as bf16 hi/lo planes.
// ---------------------------------------------------------------------------
__global__ __launch_bounds__(256) void proj_mma_kernel(const float* __restrict__ x)
{
    constexpr int APAD = 40;
    constexpr int BPAD = 208;
    __shared__ __align__(16) __nv_bfloat16 Ahi[128 * APAD];
    __shared__ __align__(16) __nv_bfloat16 Alo[128 * APAD];
    __shared__ __align__(16) __nv_bfloat16 Bhi[32 * BPAD];
    __shared__ __align__(16) __nv_bfloat16 Blo[32 * BPAD];

    const int tid  = threadIdx.x;
    const int lane = tid & 31;
    const int wid  = tid >> 5;
    const int m0   = blockIdx.x * 128;
    const int wm   = (wid & 3) * 32;
    const int wn   = (wid >> 2) * 96;

    int xrow[4], xf4[4];
    #pragma unroll
    for (int r = 0; r < 4; r++) {
        int idx = tid + r * 256;
        xrow[r] = idx >> 3;
        xf4[r]  = idx & 7;
    }
    int wrow[3], wu[3];
    #pragma unroll
    for (int r = 0; r < 3; r++) {
        int idx = tid + r * 256;
        wrow[r] = idx / 24;
        wu[r]   = idx % 24;
    }

    float c[2][12][4];
    #pragma unroll
    for (int mt = 0; mt < 2; mt++)
        #pragma unroll
        for (int nt = 0; nt < 12; nt++)
            #pragma unroll
            for (int r = 0; r < 4; r++) c[mt][nt][r] = 0.f;

    const uint32_t a_hi_base = smem_u32(Ahi);
    const uint32_t a_lo_base = smem_u32(Alo);
    const uint32_t b_hi_base = smem_u32(Bhi);
    const uint32_t b_lo_base = smem_u32(Blo);

    float4 xr[4];
    uint4  wh[3], wl[3];
    #pragma unroll
    for (int r = 0; r < 4; r++)
        xr[r] = *reinterpret_cast<const float4*>(
            &x[(size_t)(m0 + xrow[r]) * C_DIM + 0 + xf4[r] * 4]);
    #pragma unroll
    for (int r = 0; r < 3; r++) {
        wh[r] = *reinterpret_cast<const uint4*>(
            &g_wb_hi[(size_t)(0 + wrow[r]) * N_TOT + wu[r] * 8]);
        wl[r] = *reinterpret_cast<const uint4*>(
            &g_wb_lo[(size_t)(0 + wrow[r]) * N_TOT + wu[r] * 8]);
    }

    for (int cchunk = 0; cchunk < C_DIM / 32; cchunk++) {
        #pragma unroll
        for (int r = 0; r < 4; r++) {
            ushort4 hs, ls;
            split2(xr[r].x, hs.x, ls.x);
            split2(xr[r].y, hs.y, ls.y);
            split2(xr[r].z, hs.z, ls.z);
            split2(xr[r].w, hs.w, ls.w);
            *reinterpret_cast<ushort4*>(&Ahi[xrow[r] * APAD + xf4[r] * 4]) = hs;
            *reinterpret_cast<ushort4*>(&Alo[xrow[r] * APAD + xf4[r] * 4]) = ls;
        }
        #pragma unroll
        for (int r = 0; r < 3; r++) {
            *reinterpret_cast<uint4*>(&Bhi[wrow[r] * BPAD + wu[r] * 8]) = wh[r];
            *reinterpret_cast<uint4*>(&Blo[wrow[r] * BPAD + wu[r] * 8]) = wl[r];
        }
        __syncthreads();

        if (cchunk + 1 < C_DIM / 32) {
            const int kb = (cchunk + 1) * 32;
            #pragma unroll
            for (int r = 0; r < 4; r++)
                xr[r] = *reinterpret_cast<const float4*>(
                    &x[(size_t)(m0 + xrow[r]) * C_DIM + kb + xf4[r] * 4]);
            #pragma unroll
            for (int r = 0; r < 3; r++) {
                wh[r] = *reinterpret_cast<const uint4*>(
                    &g_wb_hi[(size_t)(kb + wrow[r]) * N_TOT + wu[r] * 8]);
                wl[r] = *reinterpret_cast<const uint4*>(
                    &g_wb_lo[(size_t)(kb + wrow[r]) * N_TOT + wu[r] * 8]);
            }
        }

        #pragma unroll
        for (int st = 0; st < 2; st++) {
            uint32_t ah[2][4], al[2][4];
            #pragma unroll
            for (int mt = 0; mt < 2; mt++) {
                int arow = wm + mt * 16 + (lane & 15);
                uint32_t abyte = (uint32_t)(arow * APAD + st * 16 + ((lane >> 4) << 3)) * 2;
                ldm_x4(ah[mt], a_hi_base + abyte);
                ldm_x4(al[mt], a_lo_base + abyte);
            }
            uint32_t bbyte = (uint32_t)((st * 16 + (lane & 15)) * BPAD + wn) * 2;
            #pragma unroll
            for (int nt = 0; nt < 12; nt++) {
                uint32_t bh0, bh1, bl0, bl1;
                ldm_x2t(bh0, bh1, b_hi_base + bbyte + nt * 16);
                ldm_x2t(bl0, bl1, b_lo_base + bbyte + nt * 16);
                #pragma unroll
                for (int mt = 0; mt < 2; mt++) {
                    mma_bf16(c[mt][nt], ah[mt], bh0, bh1);
                    mma_bf16(c[mt][nt], al[mt], bh0, bh1);
                    mma_bf16(c[mt][nt], ah[mt], bl0, bl1);
                }
            }
        }
        __syncthreads();
    }

    // ---- Epilogue: split C frags to bf16 hi/lo planes.
    #pragma unroll
    for (int mt = 0; mt < 2; mt++) {
        #pragma unroll
        for (int nt = 0; nt < 12; nt++) {
            int n   = wn + nt * 8;
            int mat = n >> 6;
            int hcol = (n & 63) + (lane & 3) * 2;
            __nv_bfloat16 *hp, *lp;
            if (mat == 0)      { hp = g_q_hi; lp = g_q_lo; }
            else if (mat == 1) { hp = g_k_hi; lp = g_k_lo; }
            else               { hp = g_v_hi; lp = g_v_lo; }
            int row = m0 + wm + mt * 16 + (lane >> 2);
            unsigned short h0, l0, h1, l1;
            split2(c[mt][nt][0], h0, l0);
            split2(c[mt][nt][1], h1, l1);
            size_t off = (size_t)row * H_DIM + hcol;
            *reinterpret_cast<uint32_t*>(&hp[off]) = (uint32_t)h0 | ((uint32_t)h1 << 16);
            *reinterpret_cast<uint32_t*>(&lp[off]) = (uint32_t)l0 | ((uint32_t)l1 << 16);
            split2(c[mt][nt][2], h0, l0);
            split2(c[mt][nt][3], h1, l1);
            size_t off2 = off + 8 * H_DIM;
            *reinterpret_cast<uint32_t*>(&hp[off2]) = (uint32_t)h0 | ((uint32_t)h1 << 16);
            *reinterpret_cast<uint32_t*>(&lp[off2]) = (uint32_t)l0 | ((uint32_t)l1 << 16);
        }
    }
}

// ---------------------------------------------------------------------------
// Kernel 2: causal attention on mma.sync bf16 hi/lo (3-term).
// q/k/v come pre-split as bf16 planes -> staging is pure uint4 copies.
// S-loop B operand: ldmatrix x2 NON-trans on K stored [key][h] (no transpose).
// PV-loop B operand: ldmatrix x2 trans on V stored [key][h] (as before).
// ---------------------------------------------------------------------------
#define PAD 72
__global__ __launch_bounds__(256) void attn_mma_kernel(float* __restrict__ out)
{
    __shared__ __align__(16) __nv_bfloat16 AVhi[64 * PAD];  // Q then V
    __shared__ __align__(16) __nv_bfloat16 AVlo[64 * PAD];
    __shared__ __align__(16) __nv_bfloat16 KPhi[64 * PAD];  // K then P
    __shared__ __align__(16) __nv_bfloat16 KPlo[64 * PAD];
    __shared__ float rsum[2][64];

    const int b   = blockIdx.y;
    const int qt  = 3 - blockIdx.x;
    const int tid = threadIdx.x;
    const int lane = tid & 31;
    const int wid  = tid >> 5;
    const int wm   = (wid & 3) * 16;
    const int wn   = (wid >> 2) * 32;

    const size_t base = (size_t)b * T_DIM * H_DIM;
    const float scale = 0.05103103630798288f;   // 384^-0.5

    const uint32_t av_hi = smem_u32(AVhi), av_lo = smem_u32(AVlo);
    const uint32_t kp_hi = smem_u32(KPhi), kp_lo = smem_u32(KPlo);

    // ---- Stage Q tile [64 x 64]: pure copies (2 uint4/thread/plane).
    #pragma unroll
    for (int r = 0; r < 2; r++) {
        int idx = tid + r * 256;          // 0..511
        int row = idx >> 3;
        int u   = idx & 7;
        size_t g = base + (size_t)(qt * 64 + row) * H_DIM + u * 8;
        *reinterpret_cast<uint4*>(&AVhi[row * PAD + u * 8]) =
            *reinterpret_cast<const uint4*>(&g_q_hi[g]);
        *reinterpret_cast<uint4*>(&AVlo[row * PAD + u * 8]) =
            *reinterpret_cast<const uint4*>(&g_q_lo[g]);
    }
    __syncthreads();

    // ---- Hoist Q fragments (constant across key tiles): 4 k-steps.
    uint32_t qh[4][4], ql[4][4];
    #pragma unroll
    for (int st = 0; st < 4; st++) {
        uint32_t abyte = (uint32_t)((wm + (lane & 15)) * PAD + st * 16 + ((lane >> 4) << 3)) * 2;
        ldm_x4(qh[st], av_hi + abyte);
        ldm_x4(ql[st], av_lo + abyte);
    }

    float o[4][4];
    #pragma unroll
    for (int nt = 0; nt < 4; nt++)
        #pragma unroll
        for (int r = 0; r < 4; r++) o[nt][r] = 0.f;
    float rs0 = 0.f, rs1 = 0.f;

    // S-loop non-trans B lane offset: row += lane&7, col += ((lane>>3)&1)*8.
    const uint32_t sb_lane = (uint32_t)((lane & 7) * PAD + ((lane >> 3) & 1) * 8) * 2;

    for (int kt = 0; kt <= qt; kt++) {
        __syncthreads();   // prior iter done reading AV (V/Q) and KP (P)

        // ---- Stage K (into KP) and V (into AV): pure copies, [key][h].
        #pragma unroll
        for (int r = 0; r < 2; r++) {
            int idx = tid + r * 256;
            int row = idx >> 3;
            int u   = idx & 7;
            size_t g = base + (size_t)(kt * 64 + row) * H_DIM + u * 8;
            *reinterpret_cast<uint4*>(&KPhi[row * PAD + u * 8]) =
                *reinterpret_cast<const uint4*>(&g_k_hi[g]);
            *reinterpret_cast<uint4*>(&KPlo[row * PAD + u * 8]) =
                *reinterpret_cast<const uint4*>(&g_k_lo[g]);
            *reinterpret_cast<uint4*>(&AVhi[row * PAD + u * 8]) =
                *reinterpret_cast<const uint4*>(&g_v_hi[g]);
            *reinterpret_cast<uint4*>(&AVlo[row * PAD + u * 8]) =
                *reinterpret_cast<const uint4*>(&g_v_lo[g]);
        }
        __syncthreads();

        // ---- S = Q K^T (3-term). B frags: ldm x2 non-trans on [key][h].
        float s[4][4];
        #pragma unroll
        for (int nt = 0; nt < 4; nt++)
            #pragma unroll
            for (int r = 0; r < 4; r++) s[nt][r] = 0.f;

        #pragma unroll
        for (int st = 0; st < 4; st++) {
            #pragma unroll
            for (int nt = 0; nt < 4; nt++) {
                uint32_t off = (uint32_t)((wn + nt * 8) * PAD + st * 16) * 2 + sb_lane;
                uint32_t bh0, bh1, bl0, bl1;
                ldm_x2(bh0, bh1, kp_hi + off);
                ldm_x2(bl0, bl1, kp_lo + off);
                mma_bf16(s[nt], qh[st], bh0, bh1);
                mma_bf16(s[nt], ql[st], bh0, bh1);
                mma_bf16(s[nt], qh[st], bl0, bl1);
            }
        }

        // ---- exp + causal mask; accumulate row sums.
        const bool diag = (kt == qt);
        const int rlo = (lane >> 2), rhi = rlo + 8;
        #pragma unroll
        for (int nt = 0; nt < 4; nt++) {
            int c0 = wn + nt * 8 + (lane & 3) * 2;
            float e0 = (!diag || c0     <= wm + rlo) ? __expf(s[nt][0] * scale) : 0.f;
            float e1 = (!diag || c0 + 1 <= wm + rlo) ? __expf(s[nt][1] * scale) : 0.f;
            float e2 = (!diag || c0     <= wm + rhi) ? __expf(s[nt][2] * scale) : 0.f;
            float e3 = (!diag || c0 + 1 <= wm + rhi) ? __expf(s[nt][3] * scale) : 0.f;
            s[nt][0] = e0; s[nt][1] = e1; s[nt][2] = e2; s[nt][3] = e3;
            rs0 += e0 + e1;
            rs1 += e2 + e3;
        }
        __syncthreads();   // all warps done reading K from KP

        // ---- Stage P hi/lo into KP as [q][kc].
        #pragma unroll
        for (int nt = 0; nt < 4; nt++) {
            int pcol = wn + nt * 8 + (lane & 3) * 2;
            unsigned short h0, l0, h1, l1;
            split2(s[nt][0], h0, l0);
            split2(s[nt][1], h1, l1);
            *reinterpret_cast<uint32_t*>(&KPhi[(wm + rlo) * PAD + pcol]) =
                (uint32_t)h0 | ((uint32_t)h1 << 16);
            *reinterpret_cast<uint32_t*>(&KPlo[(wm + rlo) * PAD + pcol]) =
                (uint32_t)l0 | ((uint32_t)l1 << 16);
            split2(s[nt][2], h0, l0);
            split2(s[nt][3], h1, l1);
            *reinterpret_cast<uint32_t*>(&KPhi[(wm + rhi) * PAD + pcol]) =
                (uint32_t)h0 | ((uint32_t)h1 << 16);
            *reinterpret_cast<uint32_t*>(&KPlo[(wm + rhi) * PAD + pcol]) =
                (uint32_t)l0 | ((uint32_t)l1 << 16);
        }
        __syncthreads();

        // ---- O += P V (3-term). P in KP [q][kc] (x4), V in AV [kc][h] (x2t).
        #pragma unroll
        for (int st = 0; st < 4; st++) {
            uint32_t ph[4], pl[4];
            uint32_t abyte = (uint32_t)((wm + (lane & 15)) * PAD + st * 16 + ((lane >> 4) << 3)) * 2;
            ldm_x4(ph, kp_hi + abyte);
            ldm_x4(pl, kp_lo + abyte);
            uint32_t bbyte = (uint32_t)((st * 16 + (lane & 15)) * PAD + wn) * 2;
            #pragma unroll
            for (int nt = 0; nt < 4; nt++) {
                uint32_t bh0, bh1, bl0, bl1;
                ldm_x2t(bh0, bh1, av_hi + bbyte + nt * 16);
                ldm_x2t(bl0, bl1, av_lo + bbyte + nt * 16);
                mma_bf16(o[nt], ph, bh0, bh1);
                mma_bf16(o[nt], pl, bh0, bh1);
                mma_bf16(o[nt], ph, bl0, bl1);
            }
        }
    }

    // ---- Reduce row sums.
    rs0 += __shfl_xor_sync(0xFFFFFFFF, rs0, 1);
    rs0 += __shfl_xor_sync(0xFFFFFFFF, rs0, 2);
    rs1 += __shfl_xor_sync(0xFFFFFFFF, rs1, 1);
    rs1 += __shfl_xor_sync(0xFFFFFFFF, rs1, 2);
    if ((lane & 3) == 0) {
        rsum[wid >> 2][wm + (lane >> 2)]     = rs0;
        rsum[wid >> 2][wm + (lane >> 2) + 8] = rs1;
    }
    __syncthreads();

    const float inv0 = 1.f / (rsum[0][wm + (lane >> 2)]     + rsum[1][wm + (lane >> 2)]);
    const float inv1 = 1.f / (rsum[0][wm + (lane >> 2) + 8] + rsum[1][wm + (lane >> 2) + 8]);

    const int qrow0 = qt * 64 + wm + (lane >> 2);
    #pragma unroll
    for (int nt = 0; nt < 4; nt++) {
        int col = wn + nt * 8 + (lane & 3) * 2;
        *reinterpret_cast<float2*>(
            &out[((size_t)b * T_DIM + qrow0) * H_DIM + col]) =
            make_float2(o[nt][0] * inv0, o[nt][1] * inv0);
        *reinterpret_cast<float2*>(
            &out[((size_t)b * T_DIM + qrow0 + 8) * H_DIM + col]) =
            make_float2(o[nt][2] * inv1, o[nt][3] * inv1);
    }
}

// ---------------------------------------------------------------------------
extern "C" void kernel_launch(void* const* d_in, const int* in_sizes, int n_in,
                              void* d_out, int out_size)
{
    const float* x  = (const float*)d_in[0];
    const float* Wq = (const float*)d_in[1];
    const float* Wk = (const float*)d_in[2];
    const float* Wv = (const float*)d_in[3];
    float* out = (float*)d_out;

    wprep_kernel<<<(C_DIM * N_TOT + 255) / 256, 256>>>(Wq, Wk, Wv);
    proj_mma_kernel<<<BT_ROWS / 128, 256>>>(x);
    attn_mma_kernel<<<dim3(4, B_DIM), 256>>>(out);
}

// round 14
// speedup vs baseline: 2.9692x; 1.0303x over previous
#include <cuda_runtime.h>
#include <cuda_bf16.h>
#include <stdint.h>

#define BT_ROWS 65536   // B*T
#define C_DIM   384
#define H_DIM   64
#define T_DIM   256
#define B_DIM   256
#define N_TOT   192     // q|k|v fused N

// q,k,v as bf16 hi/lo planes, [row][h] layout (row = b*T + t). 6 x 8.4 MB.
__device__ __nv_bfloat16 g_q_hi[(size_t)BT_ROWS * H_DIM];
__device__ __nv_bfloat16 g_q_lo[(size_t)BT_ROWS * H_DIM];
__device__ __nv_bfloat16 g_k_hi[(size_t)BT_ROWS * H_DIM];
__device__ __nv_bfloat16 g_k_lo[(size_t)BT_ROWS * H_DIM];
__device__ __nv_bfloat16 g_v_hi[(size_t)BT_ROWS * H_DIM];
__device__ __nv_bfloat16 g_v_lo[(size_t)BT_ROWS * H_DIM];
// Fused W in [k][n] (n = mat*64+h), bf16 hi and lo planes.
__device__ __nv_bfloat16 g_wb_hi[C_DIM * N_TOT];
__device__ __nv_bfloat16 g_wb_lo[C_DIM * N_TOT];

__device__ __forceinline__ uint32_t smem_u32(const void* p) {
    uint32_t a;
    asm("{ .reg .u64 t; cvta.to.shared.u64 t, %1; cvt.u32.u64 %0, t; }"
        : "=r"(a) : "l"(p));
    return a;
}
__device__ __forceinline__ void mma_bf16(float* c, const uint32_t* a,
                                         uint32_t b0, uint32_t b1) {
    asm volatile(
        "mma.sync.aligned.m16n8k16.row.col.f32.bf16.bf16.f32 "
        "{%0,%1,%2,%3}, {%4,%5,%6,%7}, {%8,%9}, {%0,%1,%2,%3};"
        : "+f"(c[0]), "+f"(c[1]), "+f"(c[2]), "+f"(c[3])
        : "r"(a[0]), "r"(a[1]), "r"(a[2]), "r"(a[3]), "r"(b0), "r"(b1));
}
__device__ __forceinline__ void ldm_x4(uint32_t* r, uint32_t addr) {
    asm volatile("ldmatrix.sync.aligned.m8n8.x4.shared.b16 {%0,%1,%2,%3}, [%4];"
                 : "=r"(r[0]), "=r"(r[1]), "=r"(r[2]), "=r"(r[3]) : "r"(addr));
}
__device__ __forceinline__ void ldm_x2t(uint32_t& r0, uint32_t& r1, uint32_t addr) {
    asm volatile("ldmatrix.sync.aligned.m8n8.x2.trans.shared.b16 {%0,%1}, [%2];"
                 : "=r"(r0), "=r"(r1) : "r"(addr));
}
__device__ __forceinline__ void ldm_x2(uint32_t& r0, uint32_t& r1, uint32_t addr) {
    asm volatile("ldmatrix.sync.aligned.m8n8.x2.shared.b16 {%0,%1}, [%2];"
                 : "=r"(r0), "=r"(r1) : "r"(addr));
}
__device__ __forceinline__ void split2(float v, unsigned short& h, unsigned short& l) {
    __nv_bfloat16 hb = __float2bfloat16(v);
    __nv_bfloat16 lb = __float2bfloat16(v - __bfloat162float(hb));
    h = reinterpret_cast<unsigned short&>(hb);
    l = reinterpret_cast<unsigned short&>(lb);
}

// ---------------------------------------------------------------------------
// Kernel 0: W -> bf16 hi/lo, fused [k][n] layout.
// ---------------------------------------------------------------------------
__global__ void wprep_kernel(const float* __restrict__ Wq,
                             const float* __restrict__ Wk,
                             const float* __restrict__ Wv)
{
    int idx = blockIdx.x * blockDim.x + threadIdx.x;
    if (idx >= C_DIM * N_TOT) return;
    int k = idx / N_TOT, n = idx % N_TOT;
    int mat = n >> 6, h = n & 63;
    const float* W = (mat == 0) ? Wq : (mat == 1) ? Wk : Wv;
    float v = W[(size_t)k * H_DIM + h];
    __nv_bfloat16 hi = __float2bfloat16(v);
    __nv_bfloat16 lo = __float2bfloat16(v - __bfloat162float(hi));
    g_wb_hi[idx] = hi;
    g_wb_lo[idx] = lo;
}

// ---------------------------------------------------------------------------
// Kernel 1: fused QKV projection via mma.sync bf16 (3-term hi/lo split),
// register-prefetch pipelined. Epilogue stores q/k/v as bf16 hi/lo planes.
// (unchanged from R12 passing version)
// ---------------------------------------------------------------------------
__global__ __launch_bounds__(256) void proj_mma_kernel(const float* __restrict__ x)
{
    constexpr int APAD = 40;
    constexpr int BPAD = 208;
    __shared__ __align__(16) __nv_bfloat16 Ahi[128 * APAD];
    __shared__ __align__(16) __nv_bfloat16 Alo[128 * APAD];
    __shared__ __align__(16) __nv_bfloat16 Bhi[32 * BPAD];
    __shared__ __align__(16) __nv_bfloat16 Blo[32 * BPAD];

    const int tid  = threadIdx.x;
    const int lane = tid & 31;
    const int wid  = tid >> 5;
    const int m0   = blockIdx.x * 128;
    const int wm   = (wid & 3) * 32;
    const int wn   = (wid >> 2) * 96;

    int xrow[4], xf4[4];
    #pragma unroll
    for (int r = 0; r < 4; r++) {
        int idx = tid + r * 256;
        xrow[r] = idx >> 3;
        xf4[r]  = idx & 7;
    }
    int wrow[3], wu[3];
    #pragma unroll
    for (int r = 0; r < 3; r++) {
        int idx = tid + r * 256;
        wrow[r] = idx / 24;
        wu[r]   = idx % 24;
    }

    float c[2][12][4];
    #pragma unroll
    for (int mt = 0; mt < 2; mt++)
        #pragma unroll
        for (int nt = 0; nt < 12; nt++)
            #pragma unroll
            for (int r = 0; r < 4; r++) c[mt][nt][r] = 0.f;

    const uint32_t a_hi_base = smem_u32(Ahi);
    const uint32_t a_lo_base = smem_u32(Alo);
    const uint32_t b_hi_base = smem_u32(Bhi);
    const uint32_t b_lo_base = smem_u32(Blo);

    float4 xr[4];
    uint4  wh[3], wl[3];
    #pragma unroll
    for (int r = 0; r < 4; r++)
        xr[r] = *reinterpret_cast<const float4*>(
            &x[(size_t)(m0 + xrow[r]) * C_DIM + 0 + xf4[r] * 4]);
    #pragma unroll
    for (int r = 0; r < 3; r++) {
        wh[r] = *reinterpret_cast<const uint4*>(
            &g_wb_hi[(size_t)(0 + wrow[r]) * N_TOT + wu[r] * 8]);
        wl[r] = *reinterpret_cast<const uint4*>(
            &g_wb_lo[(size_t)(0 + wrow[r]) * N_TOT + wu[r] * 8]);
    }

    for (int cchunk = 0; cchunk < C_DIM / 32; cchunk++) {
        #pragma unroll
        for (int r = 0; r < 4; r++) {
            ushort4 hs, ls;
            split2(xr[r].x, hs.x, ls.x);
            split2(xr[r].y, hs.y, ls.y);
            split2(xr[r].z, hs.z, ls.z);
            split2(xr[r].w, hs.w, ls.w);
            *reinterpret_cast<ushort4*>(&Ahi[xrow[r] * APAD + xf4[r] * 4]) = hs;
            *reinterpret_cast<ushort4*>(&Alo[xrow[r] * APAD + xf4[r] * 4]) = ls;
        }
        #pragma unroll
        for (int r = 0; r < 3; r++) {
            *reinterpret_cast<uint4*>(&Bhi[wrow[r] * BPAD + wu[r] * 8]) = wh[r];
            *reinterpret_cast<uint4*>(&Blo[wrow[r] * BPAD + wu[r] * 8]) = wl[r];
        }
        __syncthreads();

        if (cchunk + 1 < C_DIM / 32) {
            const int kb = (cchunk + 1) * 32;
            #pragma unroll
            for (int r = 0; r < 4; r++)
                xr[r] = *reinterpret_cast<const float4*>(
                    &x[(size_t)(m0 + xrow[r]) * C_DIM + kb + xf4[r] * 4]);
            #pragma unroll
            for (int r = 0; r < 3; r++) {
                wh[r] = *reinterpret_cast<const uint4*>(
                    &g_wb_hi[(size_t)(kb + wrow[r]) * N_TOT + wu[r] * 8]);
                wl[r] = *reinterpret_cast<const uint4*>(
                    &g_wb_lo[(size_t)(kb + wrow[r]) * N_TOT + wu[r] * 8]);
            }
        }

        #pragma unroll
        for (int st = 0; st < 2; st++) {
            uint32_t ah[2][4], al[2][4];
            #pragma unroll
            for (int mt = 0; mt < 2; mt++) {
                int arow = wm + mt * 16 + (lane & 15);
                uint32_t abyte = (uint32_t)(arow * APAD + st * 16 + ((lane >> 4) << 3)) * 2;
                ldm_x4(ah[mt], a_hi_base + abyte);
                ldm_x4(al[mt], a_lo_base + abyte);
            }
            uint32_t bbyte = (uint32_t)((st * 16 + (lane & 15)) * BPAD + wn) * 2;
            #pragma unroll
            for (int nt = 0; nt < 12; nt++) {
                uint32_t bh0, bh1, bl0, bl1;
                ldm_x2t(bh0, bh1, b_hi_base + bbyte + nt * 16);
                ldm_x2t(bl0, bl1, b_lo_base + bbyte + nt * 16);
                #pragma unroll
                for (int mt = 0; mt < 2; mt++) {
                    mma_bf16(c[mt][nt], ah[mt], bh0, bh1);
                    mma_bf16(c[mt][nt], al[mt], bh0, bh1);
                    mma_bf16(c[mt][nt], ah[mt], bl0, bl1);
                }
            }
        }
        __syncthreads();
    }

    #pragma unroll
    for (int mt = 0; mt < 2; mt++) {
        #pragma unroll
        for (int nt = 0; nt < 12; nt++) {
            int n   = wn + nt * 8;
            int mat = n >> 6;
            int hcol = (n & 63) + (lane & 3) * 2;
            __nv_bfloat16 *hp, *lp;
            if (mat == 0)      { hp = g_q_hi; lp = g_q_lo; }
            else if (mat == 1) { hp = g_k_hi; lp = g_k_lo; }
            else               { hp = g_v_hi; lp = g_v_lo; }
            int row = m0 + wm + mt * 16 + (lane >> 2);
            unsigned short h0, l0, h1, l1;
            split2(c[mt][nt][0], h0, l0);
            split2(c[mt][nt][1], h1, l1);
            size_t off = (size_t)row * H_DIM + hcol;
            *reinterpret_cast<uint32_t*>(&hp[off]) = (uint32_t)h0 | ((uint32_t)h1 << 16);
            *reinterpret_cast<uint32_t*>(&lp[off]) = (uint32_t)l0 | ((uint32_t)l1 << 16);
            split2(c[mt][nt][2], h0, l0);
            split2(c[mt][nt][3], h1, l1);
            size_t off2 = off + 8 * H_DIM;
            *reinterpret_cast<uint32_t*>(&hp[off2]) = (uint32_t)h0 | ((uint32_t)h1 << 16);
            *reinterpret_cast<uint32_t*>(&lp[off2]) = (uint32_t)l0 | ((uint32_t)l1 << 16);
        }
    }
}

// ---------------------------------------------------------------------------
// Kernel 2: causal attention, pipelined, DYNAMIC smem (55.8 KB > 48 KB
// static cap). Per key tile:
//   head: STS K (prefetched in regs during prev PV), issue V LDGs, sync
//   S-MMA (V latency hides underneath), exp/mask
//   STS V + STS P (P has its OWN buffer -> no hazard with K), sync
//   PV-MMA; prefetch next K into regs underneath.
// 2 barriers per tile; no exposed K/V latency. Math unchanged vs R12.
// ---------------------------------------------------------------------------
#define PAD 72
#define BUF_BYTES (64 * PAD * 2)                 // 9216 per plane
#define SMEM_ATTN (6 * BUF_BYTES + 2 * 64 * 4)   // 55808 bytes

__global__ __launch_bounds__(256) void attn_mma_kernel(float* __restrict__ out)
{
    extern __shared__ __align__(16) unsigned char dynsmem[];
    __nv_bfloat16* AVhi = reinterpret_cast<__nv_bfloat16*>(dynsmem);
    __nv_bfloat16* AVlo = reinterpret_cast<__nv_bfloat16*>(dynsmem + 1 * BUF_BYTES);
    __nv_bfloat16* Khi  = reinterpret_cast<__nv_bfloat16*>(dynsmem + 2 * BUF_BYTES);
    __nv_bfloat16* Klo  = reinterpret_cast<__nv_bfloat16*>(dynsmem + 3 * BUF_BYTES);
    __nv_bfloat16* Phi  = reinterpret_cast<__nv_bfloat16*>(dynsmem + 4 * BUF_BYTES);
    __nv_bfloat16* Plo  = reinterpret_cast<__nv_bfloat16*>(dynsmem + 5 * BUF_BYTES);
    float* rsum = reinterpret_cast<float*>(dynsmem + 6 * BUF_BYTES);  // [2][64]

    const int b   = blockIdx.y;
    const int qt  = 3 - blockIdx.x;
    const int tid = threadIdx.x;
    const int lane = tid & 31;
    const int wid  = tid >> 5;
    const int wm   = (wid & 3) * 16;
    const int wn   = (wid >> 2) * 32;

    const size_t base = (size_t)b * T_DIM * H_DIM;
    const float scale = 0.05103103630798288f;   // 384^-0.5

    const uint32_t av_hi = smem_u32(AVhi), av_lo = smem_u32(AVlo);
    const uint32_t k_hi  = smem_u32(Khi),  k_lo  = smem_u32(Klo);
    const uint32_t p_hi  = smem_u32(Phi),  p_lo  = smem_u32(Plo);

    int srow[2], su[2];
    #pragma unroll
    for (int r = 0; r < 2; r++) {
        int idx = tid + r * 256;
        srow[r] = idx >> 3;
        su[r]   = idx & 7;
    }

    // ---- Stage Q tile [64 x 64]: pure copies.
    #pragma unroll
    for (int r = 0; r < 2; r++) {
        size_t g = base + (size_t)(qt * 64 + srow[r]) * H_DIM + su[r] * 8;
        *reinterpret_cast<uint4*>(&AVhi[srow[r] * PAD + su[r] * 8]) =
            *reinterpret_cast<const uint4*>(&g_q_hi[g]);
        *reinterpret_cast<uint4*>(&AVlo[srow[r] * PAD + su[r] * 8]) =
            *reinterpret_cast<const uint4*>(&g_q_lo[g]);
    }
    // Prefetch K tile kt=0 into registers.
    uint4 krh[2], krl[2];
    #pragma unroll
    for (int r = 0; r < 2; r++) {
        size_t g = base + (size_t)(0 * 64 + srow[r]) * H_DIM + su[r] * 8;
        krh[r] = *reinterpret_cast<const uint4*>(&g_k_hi[g]);
        krl[r] = *reinterpret_cast<const uint4*>(&g_k_lo[g]);
    }
    __syncthreads();

    // ---- Hoist Q fragments: 4 k-steps.
    uint32_t qh[4][4], ql[4][4];
    #pragma unroll
    for (int st = 0; st < 4; st++) {
        uint32_t abyte = (uint32_t)((wm + (lane & 15)) * PAD + st * 16 + ((lane >> 4) << 3)) * 2;
        ldm_x4(qh[st], av_hi + abyte);
        ldm_x4(ql[st], av_lo + abyte);
    }

    float o[4][4];
    #pragma unroll
    for (int nt = 0; nt < 4; nt++)
        #pragma unroll
        for (int r = 0; r < 4; r++) o[nt][r] = 0.f;
    float rs0 = 0.f, rs1 = 0.f;

    const uint32_t sb_lane = (uint32_t)((lane & 7) * PAD + ((lane >> 3) & 1) * 8) * 2;

    for (int kt = 0; kt <= qt; kt++) {
        // ---- STS K from prefetched regs.
        #pragma unroll
        for (int r = 0; r < 2; r++) {
            *reinterpret_cast<uint4*>(&Khi[srow[r] * PAD + su[r] * 8]) = krh[r];
            *reinterpret_cast<uint4*>(&Klo[srow[r] * PAD + su[r] * 8]) = krl[r];
        }
        // ---- Issue V LDGs for this tile (consumed after exp).
        uint4 vrh[2], vrl[2];
        #pragma unroll
        for (int r = 0; r < 2; r++) {
            size_t g = base + (size_t)(kt * 64 + srow[r]) * H_DIM + su[r] * 8;
            vrh[r] = *reinterpret_cast<const uint4*>(&g_v_hi[g]);
            vrl[r] = *reinterpret_cast<const uint4*>(&g_v_lo[g]);
        }
        __syncthreads();   // K visible; prev PV (AV/P readers) done

        // ---- S = Q K^T (3-term). B frags: ldm x2 non-trans on [key][h].
        float s[4][4];
        #pragma unroll
        for (int nt = 0; nt < 4; nt++)
            #pragma unroll
            for (int r = 0; r < 4; r++) s[nt][r] = 0.f;

        #pragma unroll
        for (int st = 0; st < 4; st++) {
            #pragma unroll
            for (int nt = 0; nt < 4; nt++) {
                uint32_t off = (uint32_t)((wn + nt * 8) * PAD + st * 16) * 2 + sb_lane;
                uint32_t bh0, bh1, bl0, bl1;
                ldm_x2(bh0, bh1, k_hi + off);
                ldm_x2(bl0, bl1, k_lo + off);
                mma_bf16(s[nt], qh[st], bh0, bh1);
                mma_bf16(s[nt], ql[st], bh0, bh1);
                mma_bf16(s[nt], qh[st], bl0, bl1);
            }
        }

        // ---- exp + causal mask; accumulate row sums.
        const bool diag = (kt == qt);
        const int rlo = (lane >> 2), rhi = rlo + 8;
        #pragma unroll
        for (int nt = 0; nt < 4; nt++) {
            int c0 = wn + nt * 8 + (lane & 3) * 2;
            float e0 = (!diag || c0     <= wm + rlo) ? __expf(s[nt][0] * scale) : 0.f;
            float e1 = (!diag || c0 + 1 <= wm + rlo) ? __expf(s[nt][1] * scale) : 0.f;
            float e2 = (!diag || c0     <= wm + rhi) ? __expf(s[nt][2] * scale) : 0.f;
            float e3 = (!diag || c0 + 1 <= wm + rhi) ? __expf(s[nt][3] * scale) : 0.f;
            s[nt][0] = e0; s[nt][1] = e1; s[nt][2] = e2; s[nt][3] = e3;
            rs0 += e0 + e1;
            rs1 += e2 + e3;
        }

        // ---- STS V (AV free: Q frags hoisted, prev PV done before sync).
        #pragma unroll
        for (int r = 0; r < 2; r++) {
            *reinterpret_cast<uint4*>(&AVhi[srow[r] * PAD + su[r] * 8]) = vrh[r];
            *reinterpret_cast<uint4*>(&AVlo[srow[r] * PAD + su[r] * 8]) = vrl[r];
        }
        // ---- STS P hi/lo into its own buffer.
        #pragma unroll
        for (int nt = 0; nt < 4; nt++) {
            int pcol = wn + nt * 8 + (lane & 3) * 2;
            unsigned short h0, l0, h1, l1;
            split2(s[nt][0], h0, l0);
            split2(s[nt][1], h1, l1);
            *reinterpret_cast<uint32_t*>(&Phi[(wm + rlo) * PAD + pcol]) =
                (uint32_t)h0 | ((uint32_t)h1 << 16);
            *reinterpret_cast<uint32_t*>(&Plo[(wm + rlo) * PAD + pcol]) =
                (uint32_t)l0 | ((uint32_t)l1 << 16);
            split2(s[nt][2], h0, l0);
            split2(s[nt][3], h1, l1);
            *reinterpret_cast<uint32_t*>(&Phi[(wm + rhi) * PAD + pcol]) =
                (uint32_t)h0 | ((uint32_t)h1 << 16);
            *reinterpret_cast<uint32_t*>(&Plo[(wm + rhi) * PAD + pcol]) =
                (uint32_t)l0 | ((uint32_t)l1 << 16);
        }
        __syncthreads();   // V and P visible

        // ---- Prefetch next K (latency hides under PV-MMA).
        if (kt < qt) {
            #pragma unroll
            for (int r = 0; r < 2; r++) {
                size_t g = base + (size_t)((kt + 1) * 64 + srow[r]) * H_DIM + su[r] * 8;
                krh[r] = *reinterpret_cast<const uint4*>(&g_k_hi[g]);
                krl[r] = *reinterpret_cast<const uint4*>(&g_k_lo[g]);
            }
        }

        // ---- O += P V (3-term). P x4 from P buffer, V x2t from AV.
        #pragma unroll
        for (int st = 0; st < 4; st++) {
            uint32_t ph[4], pl[4];
            uint32_t abyte = (uint32_t)((wm + (lane & 15)) * PAD + st * 16 + ((lane >> 4) << 3)) * 2;
            ldm_x4(ph, p_hi + abyte);
            ldm_x4(pl, p_lo + abyte);
            uint32_t bbyte = (uint32_t)((st * 16 + (lane & 15)) * PAD + wn) * 2;
            #pragma unroll
            for (int nt = 0; nt < 4; nt++) {
                uint32_t bh0, bh1, bl0, bl1;
                ldm_x2t(bh0, bh1, av_hi + bbyte + nt * 16);
                ldm_x2t(bl0, bl1, av_lo + bbyte + nt * 16);
                mma_bf16(o[nt], ph, bh0, bh1);
                mma_bf16(o[nt], pl, bh0, bh1);
                mma_bf16(o[nt], ph, bl0, bl1);
            }
        }
    }

    // ---- Reduce row sums.
    rs0 += __shfl_xor_sync(0xFFFFFFFF, rs0, 1);
    rs0 += __shfl_xor_sync(0xFFFFFFFF, rs0, 2);
    rs1 += __shfl_xor_sync(0xFFFFFFFF, rs1, 1);
    rs1 += __shfl_xor_sync(0xFFFFFFFF, rs1, 2);
    if ((lane & 3) == 0) {
        rsum[(wid >> 2) * 64 + wm + (lane >> 2)]     = rs0;
        rsum[(wid >> 2) * 64 + wm + (lane >> 2) + 8] = rs1;
    }
    __syncthreads();

    const float inv0 = 1.f / (rsum[wm + (lane >> 2)]     + rsum[64 + wm + (lane >> 2)]);
    const float inv1 = 1.f / (rsum[wm + (lane >> 2) + 8] + rsum[64 + wm + (lane >> 2) + 8]);

    const int qrow0 = qt * 64 + wm + (lane >> 2);
    #pragma unroll
    for (int nt = 0; nt < 4; nt++) {
        int col = wn + nt * 8 + (lane & 3) * 2;
        *reinterpret_cast<float2*>(
            &out[((size_t)b * T_DIM + qrow0) * H_DIM + col]) =
            make_float2(o[nt][0] * inv0, o[nt][1] * inv0);
        *reinterpret_cast<float2*>(
            &out[((size_t)b * T_DIM + qrow0 + 8) * H_DIM + col]) =
            make_float2(o[nt][2] * inv1, o[nt][3] * inv1);
    }
}

// ---------------------------------------------------------------------------
extern "C" void kernel_launch(void* const* d_in, const int* in_sizes, int n_in,
                              void* d_out, int out_size)
{
    const float* x  = (const float*)d_in[0];
    const float* Wq = (const float*)d_in[1];
    const float* Wk = (const float*)d_in[2];
    const float* Wv = (const float*)d_in[3];
    float* out = (float*)d_out;

    cudaFuncSetAttribute(attn_mma_kernel,
                         cudaFuncAttributeMaxDynamicSharedMemorySize, SMEM_ATTN);

    wprep_kernel<<<(C_DIM * N_TOT + 255) / 256, 256>>>(Wq, Wk, Wv);
    proj_mma_kernel<<<BT_ROWS / 128, 256>>>(x);
    attn_mma_kernel<<<dim3(4, B_DIM), 256, SMEM_ATTN>>>(out);
}

// round 16
// speedup vs baseline: 4.6154x; 1.5544x over previous
#include <cuda_runtime.h>
#include <cuda_fp16.h>
#include <stdint.h>

#define BT_ROWS 65536   // B*T
#define C_DIM   384
#define H_DIM   64
#define T_DIM   256
#define B_DIM   256
#define N_TOT   192     // q|k|v fused N

// q as fp16 hi/lo planes; k,v as fp16 hi plane only (2-term scheme drops
// the B-side lo term). [row][h] layout (row = b*T + t).
__device__ __half g_q_hi[(size_t)BT_ROWS * H_DIM];
__device__ __half g_q_lo[(size_t)BT_ROWS * H_DIM];
__device__ __half g_k_hi[(size_t)BT_ROWS * H_DIM];
__device__ __half g_v_hi[(size_t)BT_ROWS * H_DIM];
// Fused W in [k][n] (n = mat*64+h), fp16 (hi only — B-side of 2-term).
__device__ __half g_wh[C_DIM * N_TOT];

__device__ __forceinline__ uint32_t smem_u32(const void* p) {
    uint32_t a;
    asm("{ .reg .u64 t; cvta.to.shared.u64 t, %1; cvt.u32.u64 %0, t; }"
        : "=r"(a) : "l"(p));
    return a;
}
__device__ __forceinline__ void mma_f16(float* c, const uint32_t* a,
                                        uint32_t b0, uint32_t b1) {
    asm volatile(
        "mma.sync.aligned.m16n8k16.row.col.f32.f16.f16.f32 "
        "{%0,%1,%2,%3}, {%4,%5,%6,%7}, {%8,%9}, {%0,%1,%2,%3};"
        : "+f"(c[0]), "+f"(c[1]), "+f"(c[2]), "+f"(c[3])
        : "r"(a[0]), "r"(a[1]), "r"(a[2]), "r"(a[3]), "r"(b0), "r"(b1));
}
__device__ __forceinline__ void ldm_x4(uint32_t* r, uint32_t addr) {
    asm volatile("ldmatrix.sync.aligned.m8n8.x4.shared.b16 {%0,%1,%2,%3}, [%4];"
                 : "=r"(r[0]), "=r"(r[1]), "=r"(r[2]), "=r"(r[3]) : "r"(addr));
}
__device__ __forceinline__ void ldm_x2t(uint32_t& r0, uint32_t& r1, uint32_t addr) {
    asm volatile("ldmatrix.sync.aligned.m8n8.x2.trans.shared.b16 {%0,%1}, [%2];"
                 : "=r"(r0), "=r"(r1) : "r"(addr));
}
__device__ __forceinline__ void ldm_x2(uint32_t& r0, uint32_t& r1, uint32_t addr) {
    asm volatile("ldmatrix.sync.aligned.m8n8.x2.shared.b16 {%0,%1}, [%2];"
                 : "=r"(r0), "=r"(r1) : "r"(addr));
}
// fp16 hi/lo split: hi = RN(v), lo = RN(v - hi). hi+lo accurate to ~2^-22.
__device__ __forceinline__ void split2h(float v, unsigned short& h, unsigned short& l) {
    __half hb = __float2half(v);
    __half lb = __float2half(v - __half2float(hb));
    h = reinterpret_cast<unsigned short&>(hb);
    l = reinterpret_cast<unsigned short&>(lb);
}

// ---------------------------------------------------------------------------
// Kernel 0: W -> fp16 (hi only), fused [k][n] layout.
// ---------------------------------------------------------------------------
__global__ void wprep_kernel(const float* __restrict__ Wq,
                             const float* __restrict__ Wk,
                             const float* __restrict__ Wv)
{
    int idx = blockIdx.x * blockDim.x + threadIdx.x;
    if (idx >= C_DIM * N_TOT) return;
    int k = idx / N_TOT, n = idx % N_TOT;
    int mat = n >> 6, h = n & 63;
    const float* W = (mat == 0) ? Wq : (mat == 1) ? Wk : Wv;
    g_wh[idx] = __float2half(W[(size_t)k * H_DIM + h]);
}

// ---------------------------------------------------------------------------
// Kernel 1: fused QKV projection, mma.sync fp16 2-term (x_hi*W + x_lo*W),
// register-prefetch pipelined. Epilogue: q stored hi/lo, k/v stored hi.
// ---------------------------------------------------------------------------
__global__ __launch_bounds__(256) void proj_mma_kernel(const float* __restrict__ x)
{
    constexpr int APAD = 40;
    constexpr int BPAD = 208;
    __shared__ __align__(16) __half Ahi[128 * APAD];
    __shared__ __align__(16) __half Alo[128 * APAD];
    __shared__ __align__(16) __half Bh[32 * BPAD];

    const int tid  = threadIdx.x;
    const int lane = tid & 31;
    const int wid  = tid >> 5;
    const int m0   = blockIdx.x * 128;
    const int wm   = (wid & 3) * 32;
    const int wn   = (wid >> 2) * 96;

    int xrow[4], xf4[4];
    #pragma unroll
    for (int r = 0; r < 4; r++) {
        int idx = tid + r * 256;
        xrow[r] = idx >> 3;
        xf4[r]  = idx & 7;
    }
    int wrow[3], wu[3];
    #pragma unroll
    for (int r = 0; r < 3; r++) {
        int idx = tid + r * 256;
        wrow[r] = idx / 24;
        wu[r]   = idx % 24;
    }

    float c[2][12][4];
    #pragma unroll
    for (int mt = 0; mt < 2; mt++)
        #pragma unroll
        for (int nt = 0; nt < 12; nt++)
            #pragma unroll
            for (int r = 0; r < 4; r++) c[mt][nt][r] = 0.f;

    const uint32_t a_hi_base = smem_u32(Ahi);
    const uint32_t a_lo_base = smem_u32(Alo);
    const uint32_t b_base    = smem_u32(Bh);

    float4 xr[4];
    uint4  wh[3];
    #pragma unroll
    for (int r = 0; r < 4; r++)
        xr[r] = *reinterpret_cast<const float4*>(
            &x[(size_t)(m0 + xrow[r]) * C_DIM + 0 + xf4[r] * 4]);
    #pragma unroll
    for (int r = 0; r < 3; r++)
        wh[r] = *reinterpret_cast<const uint4*>(
            &g_wh[(size_t)(0 + wrow[r]) * N_TOT + wu[r] * 8]);

    for (int cchunk = 0; cchunk < C_DIM / 32; cchunk++) {
        #pragma unroll
        for (int r = 0; r < 4; r++) {
            ushort4 hs, ls;
            split2h(xr[r].x, hs.x, ls.x);
            split2h(xr[r].y, hs.y, ls.y);
            split2h(xr[r].z, hs.z, ls.z);
            split2h(xr[r].w, hs.w, ls.w);
            *reinterpret_cast<ushort4*>(&Ahi[xrow[r] * APAD + xf4[r] * 4]) = hs;
            *reinterpret_cast<ushort4*>(&Alo[xrow[r] * APAD + xf4[r] * 4]) = ls;
        }
        #pragma unroll
        for (int r = 0; r < 3; r++)
            *reinterpret_cast<uint4*>(&Bh[wrow[r] * BPAD + wu[r] * 8]) = wh[r];
        __syncthreads();

        if (cchunk + 1 < C_DIM / 32) {
            const int kb = (cchunk + 1) * 32;
            #pragma unroll
            for (int r = 0; r < 4; r++)
                xr[r] = *reinterpret_cast<const float4*>(
                    &x[(size_t)(m0 + xrow[r]) * C_DIM + kb + xf4[r] * 4]);
            #pragma unroll
            for (int r = 0; r < 3; r++)
                wh[r] = *reinterpret_cast<const uint4*>(
                    &g_wh[(size_t)(kb + wrow[r]) * N_TOT + wu[r] * 8]);
        }

        #pragma unroll
        for (int st = 0; st < 2; st++) {
            uint32_t ah[2][4], al[2][4];
            #pragma unroll
            for (int mt = 0; mt < 2; mt++) {
                int arow = wm + mt * 16 + (lane & 15);
                uint32_t abyte = (uint32_t)(arow * APAD + st * 16 + ((lane >> 4) << 3)) * 2;
                ldm_x4(ah[mt], a_hi_base + abyte);
                ldm_x4(al[mt], a_lo_base + abyte);
            }
            uint32_t bbyte = (uint32_t)((st * 16 + (lane & 15)) * BPAD + wn) * 2;
            #pragma unroll
            for (int nt = 0; nt < 12; nt++) {
                uint32_t bh0, bh1;
                ldm_x2t(bh0, bh1, b_base + bbyte + nt * 16);
                #pragma unroll
                for (int mt = 0; mt < 2; mt++) {
                    mma_f16(c[mt][nt], ah[mt], bh0, bh1);
                    mma_f16(c[mt][nt], al[mt], bh0, bh1);
                }
            }
        }
        __syncthreads();
    }

    // ---- Epilogue: q -> hi/lo planes; k,v -> hi plane only.
    #pragma unroll
    for (int mt = 0; mt < 2; mt++) {
        #pragma unroll
        for (int nt = 0; nt < 12; nt++) {
            int n   = wn + nt * 8;
            int mat = n >> 6;
            int hcol = (n & 63) + (lane & 3) * 2;
            int row = m0 + wm + mt * 16 + (lane >> 2);
            size_t off  = (size_t)row * H_DIM + hcol;
            size_t off2 = off + 8 * H_DIM;
            if (mat == 0) {
                unsigned short h0, l0, h1, l1;
                split2h(c[mt][nt][0], h0, l0);
                split2h(c[mt][nt][1], h1, l1);
                *reinterpret_cast<uint32_t*>(&g_q_hi[off]) = (uint32_t)h0 | ((uint32_t)h1 << 16);
                *reinterpret_cast<uint32_t*>(&g_q_lo[off]) = (uint32_t)l0 | ((uint32_t)l1 << 16);
                split2h(c[mt][nt][2], h0, l0);
                split2h(c[mt][nt][3], h1, l1);
                *reinterpret_cast<uint32_t*>(&g_q_hi[off2]) = (uint32_t)h0 | ((uint32_t)h1 << 16);
                *reinterpret_cast<uint32_t*>(&g_q_lo[off2]) = (uint32_t)l0 | ((uint32_t)l1 << 16);
            } else {
                __half* hp = (mat == 1) ? g_k_hi : g_v_hi;
                __half h0 = __float2half(c[mt][nt][0]);
                __half h1 = __float2half(c[mt][nt][1]);
                *reinterpret_cast<uint32_t*>(&hp[off]) =
                    (uint32_t)reinterpret_cast<unsigned short&>(h0) |
                    ((uint32_t)reinterpret_cast<unsigned short&>(h1) << 16);
                __half h2 = __float2half(c[mt][nt][2]);
                __half h3 = __float2half(c[mt][nt][3]);
                *reinterpret_cast<uint32_t*>(&hp[off2]) =
                    (uint32_t)reinterpret_cast<unsigned short&>(h2) |
                    ((uint32_t)reinterpret_cast<unsigned short&>(h3) << 16);
            }
        }
    }
}

// ---------------------------------------------------------------------------
// Kernel 2: causal attention, fp16 2-term, pipelined (structure = R14).
// S = (q_hi + q_lo) * k_hi ; O += (p_hi + p_lo) * v_hi.
// Buffers: AVhi (Q-hi then V-hi), AVlo (Q-lo), Khi, Phi, Plo. 46.6 KB static.
// ---------------------------------------------------------------------------
#define PAD 72
__global__ __launch_bounds__(256) void attn_mma_kernel(float* __restrict__ out)
{
    __shared__ __align__(16) __half AVhi[64 * PAD];  // Q-hi then V-hi
    __shared__ __align__(16) __half AVlo[64 * PAD];  // Q-lo
    __shared__ __align__(16) __half Khi[64 * PAD];   // K-hi
    __shared__ __align__(16) __half Phi[64 * PAD];   // P-hi
    __shared__ __align__(16) __half Plo[64 * PAD];   // P-lo
    __shared__ float rsum[2][64];

    const int b   = blockIdx.y;
    const int qt  = 3 - blockIdx.x;
    const int tid = threadIdx.x;
    const int lane = tid & 31;
    const int wid  = tid >> 5;
    const int wm   = (wid & 3) * 16;
    const int wn   = (wid >> 2) * 32;

    const size_t base = (size_t)b * T_DIM * H_DIM;
    const float scale = 0.05103103630798288f;   // 384^-0.5

    const uint32_t av_hi = smem_u32(AVhi), av_lo = smem_u32(AVlo);
    const uint32_t k_hi  = smem_u32(Khi);
    const uint32_t p_hi  = smem_u32(Phi), p_lo = smem_u32(Plo);

    int srow[2], su[2];
    #pragma unroll
    for (int r = 0; r < 2; r++) {
        int idx = tid + r * 256;
        srow[r] = idx >> 3;
        su[r]   = idx & 7;
    }

    // ---- Stage Q tile [64 x 64] hi/lo: pure copies.
    #pragma unroll
    for (int r = 0; r < 2; r++) {
        size_t g = base + (size_t)(qt * 64 + srow[r]) * H_DIM + su[r] * 8;
        *reinterpret_cast<uint4*>(&AVhi[srow[r] * PAD + su[r] * 8]) =
            *reinterpret_cast<const uint4*>(&g_q_hi[g]);
        *reinterpret_cast<uint4*>(&AVlo[srow[r] * PAD + su[r] * 8]) =
            *reinterpret_cast<const uint4*>(&g_q_lo[g]);
    }
    // Prefetch K tile kt=0 (hi only).
    uint4 krh[2];
    #pragma unroll
    for (int r = 0; r < 2; r++) {
        size_t g = base + (size_t)(0 * 64 + srow[r]) * H_DIM + su[r] * 8;
        krh[r] = *reinterpret_cast<const uint4*>(&g_k_hi[g]);
    }
    __syncthreads();

    // ---- Hoist Q fragments: 4 k-steps, hi and lo.
    uint32_t qh[4][4], ql[4][4];
    #pragma unroll
    for (int st = 0; st < 4; st++) {
        uint32_t abyte = (uint32_t)((wm + (lane & 15)) * PAD + st * 16 + ((lane >> 4) << 3)) * 2;
        ldm_x4(qh[st], av_hi + abyte);
        ldm_x4(ql[st], av_lo + abyte);
    }

    float o[4][4];
    #pragma unroll
    for (int nt = 0; nt < 4; nt++)
        #pragma unroll
        for (int r = 0; r < 4; r++) o[nt][r] = 0.f;
    float rs0 = 0.f, rs1 = 0.f;

    const uint32_t sb_lane = (uint32_t)((lane & 7) * PAD + ((lane >> 3) & 1) * 8) * 2;

    for (int kt = 0; kt <= qt; kt++) {
        // ---- STS K-hi from prefetched regs.
        #pragma unroll
        for (int r = 0; r < 2; r++)
            *reinterpret_cast<uint4*>(&Khi[srow[r] * PAD + su[r] * 8]) = krh[r];
        // ---- Issue V-hi LDGs for this tile.
        uint4 vrh[2];
        #pragma unroll
        for (int r = 0; r < 2; r++) {
            size_t g = base + (size_t)(kt * 64 + srow[r]) * H_DIM + su[r] * 8;
            vrh[r] = *reinterpret_cast<const uint4*>(&g_v_hi[g]);
        }
        __syncthreads();   // K visible; prev PV readers done

        // ---- S = (q_hi + q_lo) K-hi^T. B frags: ldm x2 non-trans.
        float s[4][4];
        #pragma unroll
        for (int nt = 0; nt < 4; nt++)
            #pragma unroll
            for (int r = 0; r < 4; r++) s[nt][r] = 0.f;

        #pragma unroll
        for (int st = 0; st < 4; st++) {
            #pragma unroll
            for (int nt = 0; nt < 4; nt++) {
                uint32_t off = (uint32_t)((wn + nt * 8) * PAD + st * 16) * 2 + sb_lane;
                uint32_t bh0, bh1;
                ldm_x2(bh0, bh1, k_hi + off);
                mma_f16(s[nt], qh[st], bh0, bh1);
                mma_f16(s[nt], ql[st], bh0, bh1);
            }
        }

        // ---- exp + causal mask; accumulate row sums.
        const bool diag = (kt == qt);
        const int rlo = (lane >> 2), rhi = rlo + 8;
        #pragma unroll
        for (int nt = 0; nt < 4; nt++) {
            int c0 = wn + nt * 8 + (lane & 3) * 2;
            float e0 = (!diag || c0     <= wm + rlo) ? __expf(s[nt][0] * scale) : 0.f;
            float e1 = (!diag || c0 + 1 <= wm + rlo) ? __expf(s[nt][1] * scale) : 0.f;
            float e2 = (!diag || c0     <= wm + rhi) ? __expf(s[nt][2] * scale) : 0.f;
            float e3 = (!diag || c0 + 1 <= wm + rhi) ? __expf(s[nt][3] * scale) : 0.f;
            s[nt][0] = e0; s[nt][1] = e1; s[nt][2] = e2; s[nt][3] = e3;
            rs0 += e0 + e1;
            rs1 += e2 + e3;
        }

        // ---- STS V-hi into AVhi (Q-hi frags already hoisted).
        #pragma unroll
        for (int r = 0; r < 2; r++)
            *reinterpret_cast<uint4*>(&AVhi[srow[r] * PAD + su[r] * 8]) = vrh[r];
        // ---- STS P hi/lo (fp16 2-term split of exp values).
        #pragma unroll
        for (int nt = 0; nt < 4; nt++) {
            int pcol = wn + nt * 8 + (lane & 3) * 2;
            unsigned short h0, l0, h1, l1;
            split2h(s[nt][0], h0, l0);
            split2h(s[nt][1], h1, l1);
            *reinterpret_cast<uint32_t*>(&Phi[(wm + rlo) * PAD + pcol]) =
                (uint32_t)h0 | ((uint32_t)h1 << 16);
            *reinterpret_cast<uint32_t*>(&Plo[(wm + rlo) * PAD + pcol]) =
                (uint32_t)l0 | ((uint32_t)l1 << 16);
            split2h(s[nt][2], h0, l0);
            split2h(s[nt][3], h1, l1);
            *reinterpret_cast<uint32_t*>(&Phi[(wm + rhi) * PAD + pcol]) =
                (uint32_t)h0 | ((uint32_t)h1 << 16);
            *reinterpret_cast<uint32_t*>(&Plo[(wm + rhi) * PAD + pcol]) =
                (uint32_t)l0 | ((uint32_t)l1 << 16);
        }
        __syncthreads();   // V and P visible

        // ---- Prefetch next K-hi (latency hides under PV-MMA).
        if (kt < qt) {
            #pragma unroll
            for (int r = 0; r < 2; r++) {
                size_t g = base + (size_t)((kt + 1) * 64 + srow[r]) * H_DIM + su[r] * 8;
                krh[r] = *reinterpret_cast<const uint4*>(&g_k_hi[g]);
            }
        }

        // ---- O += (p_hi + p_lo) V-hi.
        #pragma unroll
        for (int st = 0; st < 4; st++) {
            uint32_t ph[4], pl[4];
            uint32_t abyte = (uint32_t)((wm + (lane & 15)) * PAD + st * 16 + ((lane >> 4) << 3)) * 2;
            ldm_x4(ph, p_hi + abyte);
            ldm_x4(pl, p_lo + abyte);
            uint32_t bbyte = (uint32_t)((st * 16 + (lane & 15)) * PAD + wn) * 2;
            #pragma unroll
            for (int nt = 0; nt < 4; nt++) {
                uint32_t bh0, bh1;
                ldm_x2t(bh0, bh1, av_hi + bbyte + nt * 16);
                mma_f16(o[nt], ph, bh0, bh1);
                mma_f16(o[nt], pl, bh0, bh1);
            }
        }
    }

    // ---- Reduce row sums.
    rs0 += __shfl_xor_sync(0xFFFFFFFF, rs0, 1);
    rs0 += __shfl_xor_sync(0xFFFFFFFF, rs0, 2);
    rs1 += __shfl_xor_sync(0xFFFFFFFF, rs1, 1);
    rs1 += __shfl_xor_sync(0xFFFFFFFF, rs1, 2);
    if ((lane & 3) == 0) {
        rsum[wid >> 2][wm + (lane >> 2)]     = rs0;
        rsum[wid >> 2][wm + (lane >> 2) + 8] = rs1;
    }
    __syncthreads();

    const float inv0 = 1.f / (rsum[0][wm + (lane >> 2)]     + rsum[1][wm + (lane >> 2)]);
    const float inv1 = 1.f / (rsum[0][wm + (lane >> 2) + 8] + rsum[1][wm + (lane >> 2) + 8]);

    const int qrow0 = qt * 64 + wm + (lane >> 2);
    #pragma unroll
    for (int nt = 0; nt < 4; nt++) {
        int col = wn + nt * 8 + (lane & 3) * 2;
        *reinterpret_cast<float2*>(
            &out[((size_t)b * T_DIM + qrow0) * H_DIM + col]) =
            make_float2(o[nt][0] * inv0, o[nt][1] * inv0);
        *reinterpret_cast<float2*>(
            &out[((size_t)b * T_DIM + qrow0 + 8) * H_DIM + col]) =
            make_float2(o[nt][2] * inv1, o[nt][3] * inv1);
    }
}

// ---------------------------------------------------------------------------
extern "C" void kernel_launch(void* const* d_in, const int* in_sizes, int n_in,
                              void* d_out, int out_size)
{
    const float* x  = (const float*)d_in[0];
    const float* Wq = (const float*)d_in[1];
    const float* Wk = (const float*)d_in[2];
    const float* Wv = (const float*)d_in[3];
    float* out = (float*)d_out;

    wprep_kernel<<<(C_DIM * N_TOT + 255) / 256, 256>>>(Wq, Wk, Wv);
    proj_mma_kernel<<<BT_ROWS / 128, 256>>>(x);
    attn_mma_kernel<<<dim3(4, B_DIM), 256>>>(out);
}